// round 8
// baseline (speedup 1.0000x reference)
#include <cuda_runtime.h>
#include <cuda_fp16.h>
#include <math.h>
#include <stdint.h>

#define NDEST 8192
#define NSRC  8192
#define FEATD 1024
#define TFD   256
#define EMB   64
#define HID   128
#define HEADS 2

// scratch (static device arrays: allocation-free)
__device__ __half g_fsrc_h[(size_t)NSRC * FEATD];        // 16 MB
__device__ __half g_fcW_h[TFD * FEATD];                  // 0.5 MB
__device__ __half g_decW_h[FEATD * TFD];                 // 0.5 MB
__device__ __half g_trans_h[(size_t)NSRC * TFD];         // 4 MB
__device__ float  g_hsrc[(size_t)HEADS * NSRC * HID];    // 8 MB
__device__ float  g_q[(size_t)HEADS * NDEST * HID];      // 8 MB
__device__ float  g_wc[HEADS * EMB * HID];               // 64 KB

// ---------------------------------------------------------------------------
// f32 -> f16 conversion (n multiple of 4)
// ---------------------------------------------------------------------------
__global__ void f2h_kernel(const float* __restrict__ src,
                           __half* __restrict__ dst, int n)
{
  int i = (blockIdx.x * blockDim.x + threadIdx.x) * 4;
  if (i < n) {
    float4 v = *(const float4*)(src + i);
    *(__half2*)(dst + i)     = __floats2half2_rn(v.x, v.y);
    *(__half2*)(dst + i + 2) = __floats2half2_rn(v.z, v.w);
  }
}

// ===========================================================================
// FP16 tensor-core GEMM:  C[M,N] = A[M,K] @ B[N,K]^T (+ bias[N])
// mma.m16n8k16.f16 with fp32 accum (same 10-bit mantissa as tf32 -> same
// precision, half the instructions). BM=128, BN=64, BK=32, 256 threads,
// 8 warps (4m x 2n, warp tile 32x32). Double-buffered smem; pair-permuted
// layout: fragment = one conflict-free LDS.64. Row stride 40 u32 (bank-clean
// per 16-lane phase). Requires M%128==0, N%64==0, K%32==0.
// ===========================================================================
__device__ __forceinline__ void mma_f16(float* d, const uint32_t* a, uint2 b) {
  asm volatile(
      "mma.sync.aligned.m16n8k16.row.col.f32.f16.f16.f32 "
      "{%0,%1,%2,%3}, {%4,%5,%6,%7}, {%8,%9}, {%0,%1,%2,%3};\n"
      : "+f"(d[0]), "+f"(d[1]), "+f"(d[2]), "+f"(d[3])
      : "r"(a[0]), "r"(a[1]), "r"(a[2]), "r"(a[3]), "r"(b.x), "r"(b.y));
}

#define GSM_BYTES ((2 * 128 * 40 + 2 * 64 * 40) * 4)

template<bool HALF_OUT>
__global__ __launch_bounds__(256, 2) void h16gemm_k(
    const __half* __restrict__ A, const __half* __restrict__ B,
    const float* __restrict__ bias, void* __restrict__ Cv,
    int M, int N, int K)
{
  extern __shared__ uint32_t smdyn[];
  uint32_t (*Asm)[40] = (uint32_t(*)[40])smdyn;                  // 2 x 128
  uint32_t (*Bsm)[40] = (uint32_t(*)[40])(smdyn + 2 * 128 * 40); // 2 x 64

  const int t = threadIdx.x;
  const int lane = t & 31, w = t >> 5;
  const int wm = (w & 3) * 32, wn = (w >> 2) * 32;
  const int g = lane >> 2, c = lane & 3;
  const int row0 = blockIdx.y * 128, col0 = blockIdx.x * 64;

  // global loaders: A thread -> (row t>>1, 16-k group t&1);
  //                 B thread -> (row t>>2, group bs=bq>>1, half bl=bq&1)
  const int arow = t >> 1, as = t & 1;
  const int brow = t >> 2, bq = t & 3, bs = bq >> 1, bl = bq & 1;
  const __half* pA = A + (size_t)(row0 + arow) * K + as * 16;
  const __half* pB = B + (size_t)(col0 + brow) * K + bs * 16 + bl * 8;

  uint4 qa0 = *(const uint4*)(pA);
  uint4 qa1 = *(const uint4*)(pA + 8);
  uint4 qb  = *(const uint4*)(pB);

  // prologue: stage 0.  pair-permute: slot(s,p) = 8s + 2(p&3) + (p>>2)
  {
    uint32_t* d = &Asm[arow][as * 8];
    d[0]=qa0.x; d[2]=qa0.y; d[4]=qa0.z; d[6]=qa0.w;
    d[1]=qa1.x; d[3]=qa1.y; d[5]=qa1.z; d[7]=qa1.w;
    uint32_t* e = &Bsm[brow][bs * 8 + bl];
    e[0]=qb.x; e[2]=qb.y; e[4]=qb.z; e[6]=qb.w;
  }
  __syncthreads();

  float acc[2][4][4] = {};
  int s = 0;

  for (int k0 = 0; k0 < K; k0 += 32) {
    const bool nxt = (k0 + 32 < K);
    if (nxt) {
      qa0 = *(const uint4*)(pA + k0 + 32);
      qa1 = *(const uint4*)(pA + k0 + 40);
      qb  = *(const uint4*)(pB + k0 + 32);
    }
    const uint32_t (*Ac)[40] = Asm + s * 128;
    const uint32_t (*Bc)[40] = Bsm + s * 64;

    #pragma unroll
    for (int ks = 0; ks < 2; ks++) {
      uint32_t af[2][4];
      uint2 bf[4];
      #pragma unroll
      for (int mi = 0; mi < 2; mi++) {
        uint2 lo = *(const uint2*)&Ac[wm + mi * 16 + g][ks * 8 + 2 * c];
        uint2 hi = *(const uint2*)&Ac[wm + mi * 16 + g + 8][ks * 8 + 2 * c];
        af[mi][0] = lo.x; af[mi][1] = hi.x; af[mi][2] = lo.y; af[mi][3] = hi.y;
      }
      #pragma unroll
      for (int ni = 0; ni < 4; ni++)
        bf[ni] = *(const uint2*)&Bc[wn + ni * 8 + g][ks * 8 + 2 * c];
      #pragma unroll
      for (int mi = 0; mi < 2; mi++)
        #pragma unroll
        for (int ni = 0; ni < 4; ni++)
          mma_f16(acc[mi][ni], af[mi], bf[ni]);
    }

    if (nxt) {
      uint32_t (*An)[40] = Asm + (s ^ 1) * 128;
      uint32_t (*Bn)[40] = Bsm + (s ^ 1) * 64;
      uint32_t* d = &An[arow][as * 8];
      d[0]=qa0.x; d[2]=qa0.y; d[4]=qa0.z; d[6]=qa0.w;
      d[1]=qa1.x; d[3]=qa1.y; d[5]=qa1.z; d[7]=qa1.w;
      uint32_t* e = &Bn[brow][bs * 8 + bl];
      e[0]=qb.x; e[2]=qb.y; e[4]=qb.z; e[6]=qb.w;
      __syncthreads();
      s ^= 1;
    }
  }

  #pragma unroll
  for (int mi = 0; mi < 2; mi++) {
    int r = row0 + wm + mi * 16 + g;
    #pragma unroll
    for (int ni = 0; ni < 4; ni++) {
      int cc = col0 + wn + ni * 8 + 2 * c;
      float2 bv = *(const float2*)(bias + cc);
      float* d = acc[mi][ni];
      if (HALF_OUT) {
        __half* Ch = (__half*)Cv;
        *(__half2*)(Ch + (size_t)r * N + cc) =
            __floats2half2_rn(d[0] + bv.x, d[1] + bv.y);
        *(__half2*)(Ch + (size_t)(r + 8) * N + cc) =
            __floats2half2_rn(d[2] + bv.x, d[3] + bv.y);
      } else {
        float* Cf = (float*)Cv;
        *(float2*)(Cf + (size_t)r * N + cc) =
            make_float2(d[0] + bv.x, d[1] + bv.y);
        *(float2*)(Cf + (size_t)(r + 8) * N + cc) =
            make_float2(d[2] + bv.x, d[3] + bv.y);
      }
    }
  }
}

// ---------------------------------------------------------------------------
// fp32 SGEMM for the small score-path projections (kept fp32 for accuracy).
// ---------------------------------------------------------------------------
__global__ __launch_bounds__(256) void sgemm_k(
    const float* __restrict__ A, const float* __restrict__ B,
    float* __restrict__ C,
    int M, int N, int K, long long strideB, long long strideC)
{
  const float* Bp = B + (size_t)blockIdx.z * strideB;
  float* Cp = C + (size_t)blockIdx.z * strideC;

  __shared__ float As[16][68];
  __shared__ float Bs[16][68];

  const int t  = threadIdx.x;
  const int tx = t & 15;
  const int ty = t >> 4;
  const int row0 = blockIdx.y << 6;
  const int col0 = blockIdx.x << 6;

  const int aRow = t >> 2;
  const int aK   = (t & 3) << 2;
  const int bK   = t >> 4;
  const int bN   = (t & 15) << 2;

  float acc[4][4] = {};

  for (int k0 = 0; k0 < K; k0 += 16) {
    float4 a4 = *(const float4*)(A + (size_t)(row0 + aRow) * K + (k0 + aK));
    As[aK+0][aRow] = a4.x; As[aK+1][aRow] = a4.y;
    As[aK+2][aRow] = a4.z; As[aK+3][aRow] = a4.w;
    float4 b4 = *(const float4*)(Bp + (size_t)(k0 + bK) * N + (col0 + bN));
    *(float4*)&Bs[bK][bN] = b4;
    __syncthreads();
    #pragma unroll
    for (int k = 0; k < 16; k++) {
      float4 a = *(const float4*)&As[k][ty << 2];
      float4 b = *(const float4*)&Bs[k][tx << 2];
      acc[0][0] += a.x*b.x; acc[0][1] += a.x*b.y; acc[0][2] += a.x*b.z; acc[0][3] += a.x*b.w;
      acc[1][0] += a.y*b.x; acc[1][1] += a.y*b.y; acc[1][2] += a.y*b.z; acc[1][3] += a.y*b.w;
      acc[2][0] += a.z*b.x; acc[2][1] += a.z*b.y; acc[2][2] += a.z*b.z; acc[2][3] += a.z*b.w;
      acc[3][0] += a.w*b.x; acc[3][1] += a.w*b.y; acc[3][2] += a.w*b.z; acc[3][3] += a.w*b.w;
    }
    __syncthreads();
  }

  #pragma unroll
  for (int i = 0; i < 4; i++) {
    float4 o = make_float4(acc[i][0], acc[i][1], acc[i][2], acc[i][3]);
    *(float4*)(Cp + (size_t)(row0 + (ty<<2) + i) * N + (col0 + (tx<<2))) = o;
  }
}

// ---------------------------------------------------------------------------
// Wc[h] = att_W[h] (64x128) @ att_W2[h] (128x128)
// ---------------------------------------------------------------------------
__global__ void wc_kernel(const float* __restrict__ attW,
                          const float* __restrict__ attW2,
                          float* __restrict__ wc)
{
  int h = blockIdx.y;
  int idx = blockIdx.x * blockDim.x + threadIdx.x;
  int e = idx >> 7, d = idx & 127;
  const float* W  = attW  + h * EMB * HID + e * HID;
  const float* W2 = attW2 + h * HID * HID;
  float s = 0.f;
  #pragma unroll 8
  for (int k = 0; k < HID; k++) s += W[k] * W2[k * HID + d];
  wc[h * EMB * HID + idx] = s;
}

// ---------------------------------------------------------------------------
// Sparse masked attention, one block (512 threads) per destination row m.
// out = inv0 * sum(e0*x) + inv1 * sum(e1*x): unnormalized dual accumulators,
// no Z broadcast wait. 16 warps compute scores; gather split across two
// 256-thread groups (hf). nnz ~ 82 +/- 9; SCAP=1024 (~100 sigma); chunked
// single-pass fallback keeps correctness for nnz > SCAP (never taken).
// ---------------------------------------------------------------------------
__device__ __forceinline__ float2 score_exp_pair(
    int n, const float* qsh, const float* __restrict__ hsrc, int lane)
{
  const float4* k0 = (const float4*)(hsrc + (size_t)n * HID);
  const float4* k1 = (const float4*)(hsrc + ((size_t)NSRC + n) * HID);
  const float4 a0 = ((const float4*)qsh)[lane];
  const float4 a1 = ((const float4*)qsh)[32 + lane];
  float4 b0 = k0[lane], b1 = k1[lane];
  float s0 = a0.x*b0.x + a0.y*b0.y + a0.z*b0.z + a0.w*b0.w;
  float s1 = a1.x*b1.x + a1.y*b1.y + a1.z*b1.z + a1.w*b1.w;
  #pragma unroll
  for (int o = 16; o; o >>= 1) {
    s0 += __shfl_xor_sync(0xffffffffu, s0, o);
    s1 += __shfl_xor_sync(0xffffffffu, s1, o);
  }
  float e0 = expf(s0 > 0.f ? s0 : expm1f(s0));  // exp(elu(s))
  float e1 = expf(s1 > 0.f ? s1 : expm1f(s1));
  return make_float2(e0, e1);
}

#define SCAP 1024

__global__ __launch_bounds__(512) void attn_kernel(
    const float* __restrict__ bias,
    const float* __restrict__ q,            // [2][NDEST][HID]
    const float* __restrict__ hsrc,         // [2][NSRC][HID]
    const __half* __restrict__ xh,          // [NSRC][TFD] fp16
    float* __restrict__ out)                // [NDEST][TFD]
{
  const int m = blockIdx.x;
  const int t = threadIdx.x;                 // 0..511
  const int warp = t >> 5, lane = t & 31;
  const int col = t & 255, hf = t >> 8;

  __shared__ unsigned short sidx[SCAP];        // 2 KB
  __shared__ __align__(16) float qsh[2 * HID]; // 1 KB
  __shared__ float2 ecache[SCAP];              // 8 KB
  __shared__ int s_warp[16];
  __shared__ float sZ0, sZ1;
  __shared__ float2 pacc[256];                 // 2 KB

  if (t < 256) {
    int h = t >> 7, d = t & 127;
    qsh[t] = q[((size_t)h * NDEST + m) * HID + d];
  }

  const float4* brow4 = (const float4*)(bias + (size_t)m * NSRC);

  // count nonzeros in this thread's 16 columns; warp-shuffle scan
  float4 v[4];
  int cnt = 0;
  #pragma unroll
  for (int i = 0; i < 4; i++) {
    v[i] = brow4[t * 4 + i];
    cnt += (v[i].x>0.f)+(v[i].y>0.f)+(v[i].z>0.f)+(v[i].w>0.f);
  }
  int inc = cnt;
  #pragma unroll
  for (int o = 1; o < 32; o <<= 1) {
    int u = __shfl_up_sync(0xffffffffu, inc, o);
    if (lane >= o) inc += u;
  }
  if (lane == 31) s_warp[warp] = inc;
  __syncthreads();
  int nnz = 0, woff = 0;
  #pragma unroll
  for (int i = 0; i < 16; i++) {
    int u = s_warp[i];
    nnz += u;
    if (i < warp) woff += u;
  }

  if (nnz == 0) {
    // all masked: softmax uniform over all sources (reference behavior)
    float a = 0.f;
    for (int n = hf * (NSRC/2); n < (hf + 1) * (NSRC/2); n++)
      a += __half2float(xh[(size_t)n * TFD + col]);
    __syncthreads();
    if (hf) pacc[col] = make_float2(a, 0.f);
    __syncthreads();
    if (!hf) out[(size_t)m * TFD + col] = (a + pacc[col].x) * (1.0f / NSRC);
    return;
  }

  if (nnz <= SCAP) {
    // ---------------- fast path ----------------
    int base = woff + inc - cnt;
    #pragma unroll
    for (int i = 0; i < 4; i++) {
      int b0 = t * 16 + i * 4;
      if (v[i].x > 0.f) sidx[base++] = (unsigned short)(b0 + 0);
      if (v[i].y > 0.f) sidx[base++] = (unsigned short)(b0 + 1);
      if (v[i].z > 0.f) sidx[base++] = (unsigned short)(b0 + 2);
      if (v[i].w > 0.f) sidx[base++] = (unsigned short)(b0 + 3);
    }
    __syncthreads();

    // scores -> ecache (16 warps in parallel)
    for (int j = warp; j < nnz; j += 16) {
      float2 e = score_exp_pair(sidx[j], qsh, hsrc, lane);
      if (lane == 0) ecache[j] = e;
    }
    __syncthreads();

    // warp 0 computes Z while everyone gathers
    if (warp == 0) {
      float z0 = 0.f, z1 = 0.f;
      for (int j = lane; j < nnz; j += 32) {
        float2 e = ecache[j];
        z0 += e.x; z1 += e.y;
      }
      #pragma unroll
      for (int o = 16; o; o >>= 1) {
        z0 += __shfl_xor_sync(0xffffffffu, z0, o);
        z1 += __shfl_xor_sync(0xffffffffu, z1, o);
      }
      if (lane == 0) { sZ0 = z0; sZ1 = z1; }
    }

    // unnormalized dual-accumulator gather, split halves across hf groups
    const int half = nnz >> 1;
    const int j0 = hf ? half : 0;
    const int j1 = hf ? nnz : half;
    float acc0 = 0.f, acc1 = 0.f;
    int j = j0;
    for (; j + 4 <= j1; j += 4) {
      float2 e0 = ecache[j+0], e1 = ecache[j+1];
      float2 e2 = ecache[j+2], e3 = ecache[j+3];
      float x0 = __half2float(xh[(size_t)sidx[j+0] * TFD + col]);
      float x1 = __half2float(xh[(size_t)sidx[j+1] * TFD + col]);
      float x2 = __half2float(xh[(size_t)sidx[j+2] * TFD + col]);
      float x3 = __half2float(xh[(size_t)sidx[j+3] * TFD + col]);
      acc0 += e0.x*x0 + e1.x*x1 + e2.x*x2 + e3.x*x3;
      acc1 += e0.y*x0 + e1.y*x1 + e2.y*x2 + e3.y*x3;
    }
    for (; j < j1; j++) {
      float2 e = ecache[j];
      float x = __half2float(xh[(size_t)sidx[j] * TFD + col]);
      acc0 += e.x * x; acc1 += e.y * x;
    }
    __syncthreads();
    if (hf) pacc[col] = make_float2(acc0, acc1);
    __syncthreads();
    if (!hf) {
      float2 p = pacc[col];
      out[(size_t)m * TFD + col] =
          (acc0 + p.x) * (0.5f / sZ0) + (acc1 + p.y) * (0.5f / sZ1);
    }
    return;
  }

  // -------- fallback: nnz > SCAP, chunked single pass (never expected) -----
  float acc0 = 0.f, acc1 = 0.f;
  float zp0 = 0.f, zp1 = 0.f;  // warp 0 lanes only
  for (int c0 = 0; c0 < NSRC; c0 += SCAP) {
    __syncthreads();  // protect sidx/ecache reuse
    float2 w2 = *(const float2*)(bias + (size_t)m * NSRC + c0 + t * 2);
    int ccnt = (w2.x > 0.f) + (w2.y > 0.f);
    int cinc = ccnt;
    #pragma unroll
    for (int o = 1; o < 32; o <<= 1) {
      int u = __shfl_up_sync(0xffffffffu, cinc, o);
      if (lane >= o) cinc += u;
    }
    if (lane == 31) s_warp[warp] = cinc;
    __syncthreads();
    int cn = 0, cwoff = 0;
    #pragma unroll
    for (int i = 0; i < 16; i++) {
      int u = s_warp[i];
      cn += u;
      if (i < warp) cwoff += u;
    }
    int base = cwoff + cinc - ccnt;
    int b0 = c0 + t * 2;
    if (w2.x > 0.f) sidx[base++] = (unsigned short)(b0 + 0);
    if (w2.y > 0.f) sidx[base++] = (unsigned short)(b0 + 1);
    __syncthreads();

    for (int j = warp; j < cn; j += 16) {
      float2 e = score_exp_pair(sidx[j], qsh, hsrc, lane);
      if (lane == 0) ecache[j] = e;
    }
    __syncthreads();

    if (warp == 0) {
      for (int j = lane; j < cn; j += 32) {
        float2 e = ecache[j];
        zp0 += e.x; zp1 += e.y;
      }
    }
    const int chalf = cn >> 1;
    const int j0 = hf ? chalf : 0;
    const int j1 = hf ? cn : chalf;
    for (int j = j0; j < j1; j++) {
      float2 e = ecache[j];
      float x = __half2float(xh[(size_t)sidx[j] * TFD + col]);
      acc0 += e.x * x; acc1 += e.y * x;
    }
  }
  if (warp == 0) {
    #pragma unroll
    for (int o = 16; o; o >>= 1) {
      zp0 += __shfl_xor_sync(0xffffffffu, zp0, o);
      zp1 += __shfl_xor_sync(0xffffffffu, zp1, o);
    }
    if (lane == 0) { sZ0 = zp0; sZ1 = zp1; }
  }
  __syncthreads();
  if (hf) pacc[col] = make_float2(acc0, acc1);
  __syncthreads();
  if (!hf) {
    float2 p = pacc[col];
    out[(size_t)m * TFD + col] =
        (acc0 + p.x) * (0.5f / sZ0) + (acc1 + p.y) * (0.5f / sZ1);
  }
}

// ---------------------------------------------------------------------------
extern "C" void kernel_launch(void* const* d_in, const int* in_sizes, int n_in,
                              void* d_out, int out_size)
{
  const float* bias        = (const float*)d_in[0];
  const float* emb_dest    = (const float*)d_in[1];
  const float* emb_src     = (const float*)d_in[2];
  const float* feature_src = (const float*)d_in[3];
  const float* fc_W        = (const float*)d_in[4];
  const float* fc_b        = (const float*)d_in[5];
  const float* dec_W       = (const float*)d_in[6];
  const float* dec_b       = (const float*)d_in[7];
  const float* att_W       = (const float*)d_in[8];
  const float* att_W2      = (const float*)d_in[9];

  float* out_re  = (float*)d_out;
  float* out_hat = out_re + (size_t)NDEST * TFD;

  __half *fsrc_h, *fcW_h, *decW_h, *trans_h;
  float *hsrc, *qp, *wc;
  cudaGetSymbolAddress((void**)&fsrc_h, g_fsrc_h);
  cudaGetSymbolAddress((void**)&fcW_h, g_fcW_h);
  cudaGetSymbolAddress((void**)&decW_h, g_decW_h);
  cudaGetSymbolAddress((void**)&trans_h, g_trans_h);
  cudaGetSymbolAddress((void**)&hsrc, g_hsrc);
  cudaGetSymbolAddress((void**)&qp, g_q);
  cudaGetSymbolAddress((void**)&wc, g_wc);

  cudaFuncSetAttribute(h16gemm_k<true>,
                       cudaFuncAttributeMaxDynamicSharedMemorySize, GSM_BYTES);
  cudaFuncSetAttribute(h16gemm_k<false>,
                       cudaFuncAttributeMaxDynamicSharedMemorySize, GSM_BYTES);

  // input conversions to fp16
  {
    int n1 = NSRC * FEATD;
    f2h_kernel<<<(n1/4 + 255)/256, 256>>>(feature_src, fsrc_h, n1);
    int n2 = TFD * FEATD;
    f2h_kernel<<<(n2/4 + 255)/256, 256>>>(fc_W, fcW_h, n2);
    int n3 = FEATD * TFD;
    f2h_kernel<<<(n3/4 + 255)/256, 256>>>(dec_W, decW_h, n3);
  }

  // Wc[h] = att_W[h] @ att_W2[h]
  wc_kernel<<<dim3(32, 2), 256>>>(att_W, att_W2, wc);

  // h_src[h] = emb_src @ att_W[h]   (fp32 for score accuracy)
  sgemm_k<<<dim3(HID / 64, NSRC / 64, HEADS), 256>>>(
      emb_src, att_W, hsrc, NSRC, HID, EMB,
      (long long)EMB * HID, (long long)NSRC * HID);

  // q[h] = emb_dest @ Wc[h]
  sgemm_k<<<dim3(HID / 64, NDEST / 64, HEADS), 256>>>(
      emb_dest, wc, qp, NDEST, HID, EMB,
      (long long)EMB * HID, (long long)NDEST * HID);

  // transformed = feature_src @ fc_W^T + fc_b   (fp16 mma, half output)
  h16gemm_k<true><<<dim3(TFD / 64, NSRC / 128), 256, GSM_BYTES>>>(
      fsrc_h, fcW_h, fc_b, trans_h, NSRC, TFD, FEATD);

  // feature_hat = transformed @ dec_W^T + dec_b (fp16 mma, float output)
  h16gemm_k<false><<<dim3(FEATD / 64, NSRC / 128), 256, GSM_BYTES>>>(
      trans_h, decW_h, dec_b, out_hat, NSRC, FEATD, TFD);

  // sparse masked attention + aggregation
  attn_kernel<<<NDEST, 512>>>(bias, qp, hsrc, trans_h, out_re);
}

// round 9
// speedup vs baseline: 1.1613x; 1.1613x over previous
#include <cuda_runtime.h>
#include <cuda_fp16.h>
#include <math.h>
#include <stdint.h>

#define NDEST 8192
#define NSRC  8192
#define FEATD 1024
#define TFD   256
#define EMB   64
#define HID   128
#define HEADS 2

// scratch (static device arrays: allocation-free)
__device__ __half g_fcW_h[TFD * FEATD];                  // 0.5 MB
__device__ __half g_decW_h[FEATD * TFD];                 // 0.5 MB
__device__ __half g_trans_h[(size_t)NSRC * TFD];         // 4 MB
__device__ float  g_hsrc[(size_t)HEADS * NSRC * HID];    // 8 MB
__device__ float  g_q[(size_t)HEADS * NDEST * HID];      // 8 MB
__device__ float  g_wc[HEADS * EMB * HID];               // 64 KB

// ---------------------------------------------------------------------------
// f32 -> f16 conversion (n multiple of 4) — weights only (small)
// ---------------------------------------------------------------------------
__global__ void f2h_kernel(const float* __restrict__ src,
                           __half* __restrict__ dst, int n)
{
  int i = (blockIdx.x * blockDim.x + threadIdx.x) * 4;
  if (i < n) {
    float4 v = *(const float4*)(src + i);
    *(__half2*)(dst + i)     = __floats2half2_rn(v.x, v.y);
    *(__half2*)(dst + i + 2) = __floats2half2_rn(v.z, v.w);
  }
}

// ===========================================================================
// FP16 tensor-core GEMM:  C[M,N] = A[M,K] @ B[N,K]^T (+ bias[N])
// mma.m16n8k16.f16, fp32 accum. BM=128, BN=64, BK=32, 256 threads, 8 warps
// (4m x 2n, warp tile 32x32). Double-buffered smem; pair-permuted layout:
// fragment = one conflict-free LDS.64 (row stride 40 u32).
// A_FLOAT: A is fp32 in gmem, converted to fp16 during the smem store
// (no separate conversion pass). Requires M%128==0, N%64==0, K%32==0.
// ===========================================================================
__device__ __forceinline__ void mma_f16(float* d, const uint32_t* a, uint2 b) {
  asm volatile(
      "mma.sync.aligned.m16n8k16.row.col.f32.f16.f16.f32 "
      "{%0,%1,%2,%3}, {%4,%5,%6,%7}, {%8,%9}, {%0,%1,%2,%3};\n"
      : "+f"(d[0]), "+f"(d[1]), "+f"(d[2]), "+f"(d[3])
      : "r"(a[0]), "r"(a[1]), "r"(a[2]), "r"(a[3]), "r"(b.x), "r"(b.y));
}

#define GSM_BYTES ((2 * 128 * 40 + 2 * 64 * 40) * 4)

__device__ __forceinline__ uint32_t h2u(__half2 h) {
  return *(uint32_t*)&h;
}

template<bool A_FLOAT, bool HALF_OUT>
__global__ __launch_bounds__(256, 2) void h16gemm_k(
    const void* __restrict__ Av, const __half* __restrict__ B,
    const float* __restrict__ bias, void* __restrict__ Cv,
    int M, int N, int K)
{
  extern __shared__ uint32_t smdyn[];
  uint32_t (*Asm)[40] = (uint32_t(*)[40])smdyn;                  // 2 x 128
  uint32_t (*Bsm)[40] = (uint32_t(*)[40])(smdyn + 2 * 128 * 40); // 2 x 64

  const int t = threadIdx.x;
  const int lane = t & 31, w = t >> 5;
  const int wm = (w & 3) * 32, wn = (w >> 2) * 32;
  const int g = lane >> 2, c = lane & 3;
  const int row0 = blockIdx.y * 128, col0 = blockIdx.x * 64;

  // A thread -> (row t>>1, 16-k group t&1); B thread -> (row t>>2, 8-k slot)
  const int arow = t >> 1, as = t & 1;
  const int brow = t >> 2, bq = t & 3, bs = bq >> 1, bl = bq & 1;

  const float*  pAf = (const float*)Av  + (size_t)(row0 + arow) * K + as * 16;
  const __half* pAh = (const __half*)Av + (size_t)(row0 + arow) * K + as * 16;
  const __half* pB  = B + (size_t)(col0 + brow) * K + bs * 16 + bl * 8;

  // prefetch registers (union-style: only one A path used per instantiation)
  float4 fa0, fa1, fa2, fa3;
  uint4  qa0, qa1;
  uint4  qb;

  if (A_FLOAT) {
    fa0 = *(const float4*)(pAf);
    fa1 = *(const float4*)(pAf + 4);
    fa2 = *(const float4*)(pAf + 8);
    fa3 = *(const float4*)(pAf + 12);
  } else {
    qa0 = *(const uint4*)(pAh);
    qa1 = *(const uint4*)(pAh + 8);
  }
  qb = *(const uint4*)(pB);

  // store stage: pair-permute slots d[2j]=pair(2j,2j+1), d[2j+1]=pair(8+2j,..)
  auto storeA = [&](uint32_t (*An)[40]) {
    uint32_t* d = &An[arow][as * 8];
    if (A_FLOAT) {
      d[0] = h2u(__floats2half2_rn(fa0.x, fa0.y));
      d[2] = h2u(__floats2half2_rn(fa0.z, fa0.w));
      d[4] = h2u(__floats2half2_rn(fa1.x, fa1.y));
      d[6] = h2u(__floats2half2_rn(fa1.z, fa1.w));
      d[1] = h2u(__floats2half2_rn(fa2.x, fa2.y));
      d[3] = h2u(__floats2half2_rn(fa2.z, fa2.w));
      d[5] = h2u(__floats2half2_rn(fa3.x, fa3.y));
      d[7] = h2u(__floats2half2_rn(fa3.z, fa3.w));
    } else {
      d[0]=qa0.x; d[2]=qa0.y; d[4]=qa0.z; d[6]=qa0.w;
      d[1]=qa1.x; d[3]=qa1.y; d[5]=qa1.z; d[7]=qa1.w;
    }
  };
  auto storeB = [&](uint32_t (*Bn)[40]) {
    uint32_t* e = &Bn[brow][bs * 8 + bl];
    e[0]=qb.x; e[2]=qb.y; e[4]=qb.z; e[6]=qb.w;
  };

  storeA(Asm);
  storeB(Bsm);
  __syncthreads();

  float acc[2][4][4] = {};
  int s = 0;

  for (int k0 = 0; k0 < K; k0 += 32) {
    const bool nxt = (k0 + 32 < K);
    if (nxt) {
      if (A_FLOAT) {
        fa0 = *(const float4*)(pAf + k0 + 32);
        fa1 = *(const float4*)(pAf + k0 + 36);
        fa2 = *(const float4*)(pAf + k0 + 40);
        fa3 = *(const float4*)(pAf + k0 + 44);
      } else {
        qa0 = *(const uint4*)(pAh + k0 + 32);
        qa1 = *(const uint4*)(pAh + k0 + 40);
      }
      qb = *(const uint4*)(pB + k0 + 32);
    }
    const uint32_t (*Ac)[40] = Asm + s * 128;
    const uint32_t (*Bc)[40] = Bsm + s * 64;

    #pragma unroll
    for (int ks = 0; ks < 2; ks++) {
      uint32_t af[2][4];
      uint2 bf[4];
      #pragma unroll
      for (int mi = 0; mi < 2; mi++) {
        uint2 lo = *(const uint2*)&Ac[wm + mi * 16 + g][ks * 8 + 2 * c];
        uint2 hi = *(const uint2*)&Ac[wm + mi * 16 + g + 8][ks * 8 + 2 * c];
        af[mi][0] = lo.x; af[mi][1] = hi.x; af[mi][2] = lo.y; af[mi][3] = hi.y;
      }
      #pragma unroll
      for (int ni = 0; ni < 4; ni++)
        bf[ni] = *(const uint2*)&Bc[wn + ni * 8 + g][ks * 8 + 2 * c];
      #pragma unroll
      for (int mi = 0; mi < 2; mi++)
        #pragma unroll
        for (int ni = 0; ni < 4; ni++)
          mma_f16(acc[mi][ni], af[mi], bf[ni]);
    }

    if (nxt) {
      storeA(Asm + (s ^ 1) * 128);
      storeB(Bsm + (s ^ 1) * 64);
      __syncthreads();
      s ^= 1;
    }
  }

  #pragma unroll
  for (int mi = 0; mi < 2; mi++) {
    int r = row0 + wm + mi * 16 + g;
    #pragma unroll
    for (int ni = 0; ni < 4; ni++) {
      int cc = col0 + wn + ni * 8 + 2 * c;
      float2 bv = *(const float2*)(bias + cc);
      float* d = acc[mi][ni];
      if (HALF_OUT) {
        __half* Ch = (__half*)Cv;
        *(__half2*)(Ch + (size_t)r * N + cc) =
            __floats2half2_rn(d[0] + bv.x, d[1] + bv.y);
        *(__half2*)(Ch + (size_t)(r + 8) * N + cc) =
            __floats2half2_rn(d[2] + bv.x, d[3] + bv.y);
      } else {
        float* Cf = (float*)Cv;
        *(float2*)(Cf + (size_t)r * N + cc) =
            make_float2(d[0] + bv.x, d[1] + bv.y);
        *(float2*)(Cf + (size_t)(r + 8) * N + cc) =
            make_float2(d[2] + bv.x, d[3] + bv.y);
      }
    }
  }
}

// ---------------------------------------------------------------------------
// Merged fp32 SGEMM for BOTH score-path projections in one launch.
// z = 0,1: hsrc[h] = emb_src  @ att_W[h]
// z = 2,3: q[h]    = emb_dest @ wc[h]
// C[8192,128] = A[8192,64] @ B[64,128]. 64x64 tile, BK=16.
// ---------------------------------------------------------------------------
__global__ __launch_bounds__(256) void sgemm4_k(
    const float* __restrict__ emb_src, const float* __restrict__ emb_dest,
    const float* __restrict__ attW, const float* __restrict__ wc,
    float* __restrict__ hsrc, float* __restrict__ q)
{
  const int z = blockIdx.z;
  const int head = z & 1, sel = z >> 1;
  const int N = HID, K = EMB;
  const float* A  = sel ? emb_dest : emb_src;
  const float* Bp = (sel ? wc : attW) + head * EMB * HID;
  float* Cp = (sel ? q : hsrc) + (size_t)head * NSRC * HID;

  __shared__ float As[16][68];
  __shared__ float Bs[16][68];

  const int t  = threadIdx.x;
  const int tx = t & 15;
  const int ty = t >> 4;
  const int row0 = blockIdx.y << 6;
  const int col0 = blockIdx.x << 6;

  const int aRow = t >> 2;
  const int aK   = (t & 3) << 2;
  const int bK   = t >> 4;
  const int bN   = (t & 15) << 2;

  float acc[4][4] = {};

  for (int k0 = 0; k0 < K; k0 += 16) {
    float4 a4 = *(const float4*)(A + (size_t)(row0 + aRow) * K + (k0 + aK));
    As[aK+0][aRow] = a4.x; As[aK+1][aRow] = a4.y;
    As[aK+2][aRow] = a4.z; As[aK+3][aRow] = a4.w;
    float4 b4 = *(const float4*)(Bp + (size_t)(k0 + bK) * N + (col0 + bN));
    *(float4*)&Bs[bK][bN] = b4;
    __syncthreads();
    #pragma unroll
    for (int k = 0; k < 16; k++) {
      float4 a = *(const float4*)&As[k][ty << 2];
      float4 b = *(const float4*)&Bs[k][tx << 2];
      acc[0][0] += a.x*b.x; acc[0][1] += a.x*b.y; acc[0][2] += a.x*b.z; acc[0][3] += a.x*b.w;
      acc[1][0] += a.y*b.x; acc[1][1] += a.y*b.y; acc[1][2] += a.y*b.z; acc[1][3] += a.y*b.w;
      acc[2][0] += a.z*b.x; acc[2][1] += a.z*b.y; acc[2][2] += a.z*b.z; acc[2][3] += a.z*b.w;
      acc[3][0] += a.w*b.x; acc[3][1] += a.w*b.y; acc[3][2] += a.w*b.z; acc[3][3] += a.w*b.w;
    }
    __syncthreads();
  }

  #pragma unroll
  for (int i = 0; i < 4; i++) {
    float4 o = make_float4(acc[i][0], acc[i][1], acc[i][2], acc[i][3]);
    *(float4*)(Cp + (size_t)(row0 + (ty<<2) + i) * N + (col0 + (tx<<2))) = o;
  }
}

// ---------------------------------------------------------------------------
// Wc[h] = att_W[h] (64x128) @ att_W2[h] (128x128)
// One block per (h,e) row: W row in smem, coalesced W2 column stream, MLP 16.
// ---------------------------------------------------------------------------
__global__ __launch_bounds__(128) void wc_kernel(
    const float* __restrict__ attW, const float* __restrict__ attW2,
    float* __restrict__ wc)
{
  const int b = blockIdx.x;              // 0..127
  const int h = b >> 6, e = b & 63;
  const int d = threadIdx.x;             // 0..127
  __shared__ float Wsh[HID];
  Wsh[d] = attW[h * EMB * HID + e * HID + d];
  __syncthreads();
  const float* W2 = attW2 + h * HID * HID;
  float s = 0.f;
  #pragma unroll 16
  for (int k = 0; k < HID; k++) s += Wsh[k] * W2[k * HID + d];
  wc[h * EMB * HID + e * HID + d] = s;
}

// ---------------------------------------------------------------------------
// Sparse masked attention, one block (256 threads) per destination row m.
// Dual unnormalized accumulators: out = inv0*sum(e0*x) + inv1*sum(e1*x).
// t0 reduces Z concurrently with the gather; fp16 gather halves L2 traffic.
// nnz ~ Binomial(8192,0.01) = 82 +/- 9; SCAP=1024 (~100 sigma); chunked
// single-pass fallback keeps correctness for nnz > SCAP (never taken).
// ---------------------------------------------------------------------------
__device__ __forceinline__ float2 score_exp_pair(
    int n, const float* qsh, const float* __restrict__ hsrc, int lane)
{
  const float4* k0 = (const float4*)(hsrc + (size_t)n * HID);
  const float4* k1 = (const float4*)(hsrc + ((size_t)NSRC + n) * HID);
  const float4 a0 = ((const float4*)qsh)[lane];
  const float4 a1 = ((const float4*)qsh)[32 + lane];
  float4 b0 = k0[lane], b1 = k1[lane];
  float s0 = a0.x*b0.x + a0.y*b0.y + a0.z*b0.z + a0.w*b0.w;
  float s1 = a1.x*b1.x + a1.y*b1.y + a1.z*b1.z + a1.w*b1.w;
  #pragma unroll
  for (int o = 16; o; o >>= 1) {
    s0 += __shfl_xor_sync(0xffffffffu, s0, o);
    s1 += __shfl_xor_sync(0xffffffffu, s1, o);
  }
  float e0 = expf(s0 > 0.f ? s0 : expm1f(s0));  // exp(elu(s))
  float e1 = expf(s1 > 0.f ? s1 : expm1f(s1));
  return make_float2(e0, e1);
}

#define SCAP 1024

__global__ __launch_bounds__(256) void attn_kernel(
    const float* __restrict__ bias,
    const float* __restrict__ q,            // [2][NDEST][HID]
    const float* __restrict__ hsrc,         // [2][NSRC][HID]
    const __half* __restrict__ xh,          // [NSRC][TFD] fp16
    float* __restrict__ out)                // [NDEST][TFD]
{
  const int m = blockIdx.x;
  const int t = threadIdx.x;
  const int warp = t >> 5, lane = t & 31;

  __shared__ unsigned short sidx[SCAP];        // 2 KB
  __shared__ __align__(16) float qsh[2 * HID]; // 1 KB
  __shared__ float2 ecache[SCAP];              // 8 KB
  __shared__ int s_warp[8];
  __shared__ float red[16];
  __shared__ float sZ0, sZ1;

  {
    int h = t >> 7, d = t & 127;
    qsh[t] = q[((size_t)h * NDEST + m) * HID + d];
  }

  const float4* brow4 = (const float4*)(bias + (size_t)m * NSRC);

  // count nonzeros in this thread's 32 columns; warp-shuffle scan
  float4 v[8];
  int cnt = 0;
  #pragma unroll
  for (int i = 0; i < 8; i++) {
    v[i] = brow4[t * 8 + i];
    cnt += (v[i].x>0.f)+(v[i].y>0.f)+(v[i].z>0.f)+(v[i].w>0.f);
  }
  int inc = cnt;
  #pragma unroll
  for (int o = 1; o < 32; o <<= 1) {
    int u = __shfl_up_sync(0xffffffffu, inc, o);
    if (lane >= o) inc += u;
  }
  if (lane == 31) s_warp[warp] = inc;
  __syncthreads();
  int nnz = 0, woff = 0;
  #pragma unroll
  for (int i = 0; i < 8; i++) {
    int u = s_warp[i];
    nnz += u;
    if (i < warp) woff += u;
  }

  if (nnz == 0) {
    // all masked: softmax uniform over all sources (reference behavior)
    float acc = 0.f;
    for (int n = 0; n < NSRC; n++)
      acc += __half2float(xh[(size_t)n * TFD + t]);
    out[(size_t)m * TFD + t] = acc * (1.0f / NSRC);
    return;
  }

  if (nnz <= SCAP) {
    // ---------------- fast path ----------------
    int base = woff + inc - cnt;
    #pragma unroll
    for (int i = 0; i < 8; i++) {
      int b0 = t * 32 + i * 4;
      if (v[i].x > 0.f) sidx[base++] = (unsigned short)(b0 + 0);
      if (v[i].y > 0.f) sidx[base++] = (unsigned short)(b0 + 1);
      if (v[i].z > 0.f) sidx[base++] = (unsigned short)(b0 + 2);
      if (v[i].w > 0.f) sidx[base++] = (unsigned short)(b0 + 3);
    }
    __syncthreads();

    // scores -> ecache (8 warps)
    for (int j = warp; j < nnz; j += 8) {
      float2 e = score_exp_pair(sidx[j], qsh, hsrc, lane);
      if (lane == 0) ecache[j] = e;
    }
    __syncthreads();

    // t==0's warp reduces Z while all threads gather (sZ read after barrier)
    if (warp == 0) {
      float z0 = 0.f, z1 = 0.f;
      for (int j = lane; j < nnz; j += 32) {
        float2 e = ecache[j];
        z0 += e.x; z1 += e.y;
      }
      #pragma unroll
      for (int o = 16; o; o >>= 1) {
        z0 += __shfl_xor_sync(0xffffffffu, z0, o);
        z1 += __shfl_xor_sync(0xffffffffu, z1, o);
      }
      if (lane == 0) { sZ0 = z0; sZ1 = z1; }
    }

    // unnormalized dual-accumulator gather, 8-wide for MLP
    float acc0 = 0.f, acc1 = 0.f;
    int j = 0;
    for (; j + 8 <= nnz; j += 8) {
      float x0 = __half2float(xh[(size_t)sidx[j+0] * TFD + t]);
      float x1 = __half2float(xh[(size_t)sidx[j+1] * TFD + t]);
      float x2 = __half2float(xh[(size_t)sidx[j+2] * TFD + t]);
      float x3 = __half2float(xh[(size_t)sidx[j+3] * TFD + t]);
      float x4 = __half2float(xh[(size_t)sidx[j+4] * TFD + t]);
      float x5 = __half2float(xh[(size_t)sidx[j+5] * TFD + t]);
      float x6 = __half2float(xh[(size_t)sidx[j+6] * TFD + t]);
      float x7 = __half2float(xh[(size_t)sidx[j+7] * TFD + t]);
      float2 e0 = ecache[j+0], e1 = ecache[j+1];
      float2 e2 = ecache[j+2], e3 = ecache[j+3];
      float2 e4 = ecache[j+4], e5 = ecache[j+5];
      float2 e6 = ecache[j+6], e7 = ecache[j+7];
      acc0 += e0.x*x0 + e1.x*x1 + e2.x*x2 + e3.x*x3
            + e4.x*x4 + e5.x*x5 + e6.x*x6 + e7.x*x7;
      acc1 += e0.y*x0 + e1.y*x1 + e2.y*x2 + e3.y*x3
            + e4.y*x4 + e5.y*x5 + e6.y*x6 + e7.y*x7;
    }
    for (; j < nnz; j++) {
      float2 e = ecache[j];
      float x = __half2float(xh[(size_t)sidx[j] * TFD + t]);
      acc0 += e.x * x; acc1 += e.y * x;
    }
    __syncthreads();
    out[(size_t)m * TFD + t] = acc0 * (0.5f / sZ0) + acc1 * (0.5f / sZ1);
    return;
  }

  // -------- fallback: nnz > SCAP, chunked single pass (never expected) -----
  float acc0 = 0.f, acc1 = 0.f;
  float zp0 = 0.f, zp1 = 0.f;  // per-warp partials via lane 0
  for (int c0 = 0; c0 < NSRC; c0 += SCAP) {
    __syncthreads();  // protect sidx/ecache reuse
    float4 w0 = brow4[c0 / 4 + t];
    int ccnt = (w0.x>0.f)+(w0.y>0.f)+(w0.z>0.f)+(w0.w>0.f);
    int cinc = ccnt;
    #pragma unroll
    for (int o = 1; o < 32; o <<= 1) {
      int u = __shfl_up_sync(0xffffffffu, cinc, o);
      if (lane >= o) cinc += u;
    }
    if (lane == 31) s_warp[warp] = cinc;
    __syncthreads();
    int cn = 0, cwoff = 0;
    #pragma unroll
    for (int i = 0; i < 8; i++) {
      int u = s_warp[i];
      cn += u;
      if (i < warp) cwoff += u;
    }
    int base = cwoff + cinc - ccnt;
    int b0 = c0 + t * 4;
    if (w0.x > 0.f) sidx[base++] = (unsigned short)(b0 + 0);
    if (w0.y > 0.f) sidx[base++] = (unsigned short)(b0 + 1);
    if (w0.z > 0.f) sidx[base++] = (unsigned short)(b0 + 2);
    if (w0.w > 0.f) sidx[base++] = (unsigned short)(b0 + 3);
    __syncthreads();

    for (int j = warp; j < cn; j += 8) {
      float2 e = score_exp_pair(sidx[j], qsh, hsrc, lane);
      if (lane == 0) { ecache[j] = e; zp0 += e.x; zp1 += e.y; }
    }
    __syncthreads();
    for (int j = 0; j < cn; j++) {
      float2 e = ecache[j];
      float x = __half2float(xh[(size_t)sidx[j] * TFD + t]);
      acc0 += e.x * x; acc1 += e.y * x;
    }
  }
  if (lane == 0) { red[warp] = zp0; red[8 + warp] = zp1; }
  __syncthreads();
  if (t == 0) {
    float z0 = 0.f, z1 = 0.f;
    #pragma unroll
    for (int wi = 0; wi < 8; wi++) { z0 += red[wi]; z1 += red[8 + wi]; }
    sZ0 = z0; sZ1 = z1;
  }
  __syncthreads();
  out[(size_t)m * TFD + t] = acc0 * (0.5f / sZ0) + acc1 * (0.5f / sZ1);
}

// ---------------------------------------------------------------------------
extern "C" void kernel_launch(void* const* d_in, const int* in_sizes, int n_in,
                              void* d_out, int out_size)
{
  const float* bias        = (const float*)d_in[0];
  const float* emb_dest    = (const float*)d_in[1];
  const float* emb_src     = (const float*)d_in[2];
  const float* feature_src = (const float*)d_in[3];
  const float* fc_W        = (const float*)d_in[4];
  const float* fc_b        = (const float*)d_in[5];
  const float* dec_W       = (const float*)d_in[6];
  const float* dec_b       = (const float*)d_in[7];
  const float* att_W       = (const float*)d_in[8];
  const float* att_W2      = (const float*)d_in[9];

  float* out_re  = (float*)d_out;
  float* out_hat = out_re + (size_t)NDEST * TFD;

  __half *fcW_h, *decW_h, *trans_h;
  float *hsrc, *qp, *wc;
  cudaGetSymbolAddress((void**)&fcW_h, g_fcW_h);
  cudaGetSymbolAddress((void**)&decW_h, g_decW_h);
  cudaGetSymbolAddress((void**)&trans_h, g_trans_h);
  cudaGetSymbolAddress((void**)&hsrc, g_hsrc);
  cudaGetSymbolAddress((void**)&qp, g_q);
  cudaGetSymbolAddress((void**)&wc, g_wc);

  cudaFuncSetAttribute(h16gemm_k<true, true>,
                       cudaFuncAttributeMaxDynamicSharedMemorySize, GSM_BYTES);
  cudaFuncSetAttribute(h16gemm_k<false, false>,
                       cudaFuncAttributeMaxDynamicSharedMemorySize, GSM_BYTES);

  // small weight conversions to fp16
  f2h_kernel<<<(TFD*FEATD/4 + 255)/256, 256>>>(fc_W, fcW_h, TFD*FEATD);
  f2h_kernel<<<(FEATD*TFD/4 + 255)/256, 256>>>(dec_W, decW_h, FEATD*TFD);

  // Wc[h] = att_W[h] @ att_W2[h]
  wc_kernel<<<128, 128>>>(att_W, att_W2, wc);

  // hsrc + q in one batched launch (fp32 for score accuracy)
  sgemm4_k<<<dim3(HID / 64, NSRC / 64, 4), 256>>>(
      emb_src, emb_dest, att_W, wc, hsrc, qp);

  // transformed = feature_src @ fc_W^T + fc_b (fp32 A converted in-kernel)
  h16gemm_k<true, true><<<dim3(TFD / 64, NSRC / 128), 256, GSM_BYTES>>>(
      feature_src, fcW_h, fc_b, trans_h, NSRC, TFD, FEATD);

  // feature_hat = transformed @ dec_W^T + dec_b
  h16gemm_k<false, false><<<dim3(FEATD / 64, NSRC / 128), 256, GSM_BYTES>>>(
      trans_h, decW_h, dec_b, out_hat, NSRC, FEATD, TFD);

  // sparse masked attention + aggregation
  attn_kernel<<<NDEST, 256>>>(bias, qp, hsrc, trans_h, out_re);
}

// round 10
// speedup vs baseline: 1.2550x; 1.0807x over previous
#include <cuda_runtime.h>
#include <cuda_fp16.h>
#include <math.h>
#include <stdint.h>

#define NDEST 8192
#define NSRC  8192
#define FEATD 1024
#define TFD   256
#define EMB   64
#define HID   128
#define HEADS 2

// scratch (static device arrays: allocation-free)
__device__ __half g_fcW_h[TFD * FEATD];                  // 0.5 MB
__device__ __half g_decW_h[FEATD * TFD];                 // 0.5 MB
__device__ __half g_trans_h[(size_t)NSRC * TFD];         // 4 MB
__device__ __half g_hsrc_h[(size_t)NSRC * 2 * HID];      // 4 MB, [n][head][128]
__device__ float  g_q[(size_t)NDEST * 2 * HID];          // 8 MB, [m][head][128]
__device__ float  g_wc[HEADS * EMB * HID];               // 64 KB

// ---------------------------------------------------------------------------
// f32 -> f16 conversion (n multiple of 4) — weights only (small)
// ---------------------------------------------------------------------------
__global__ void f2h_kernel(const float* __restrict__ src,
                           __half* __restrict__ dst, int n)
{
  int i = (blockIdx.x * blockDim.x + threadIdx.x) * 4;
  if (i < n) {
    float4 v = *(const float4*)(src + i);
    *(__half2*)(dst + i)     = __floats2half2_rn(v.x, v.y);
    *(__half2*)(dst + i + 2) = __floats2half2_rn(v.z, v.w);
  }
}

__device__ __forceinline__ uint32_t h2u(__half2 h) {
  return *(uint32_t*)&h;
}

// ===========================================================================
// FP16 tensor-core GEMM:  C[M,N] = A[M,K] @ B[N,K]^T (+ bias[N])
// mma.m16n8k16.f16, fp32 accum. BM=128, BN=64, BK=32, 256 threads, 8 warps
// (4m x 2n, warp tile 32x32). Double-buffered smem; pair-permuted layout:
// fragment = one conflict-free LDS.64 (row stride 40 u32).
// A_FLOAT: A fp32 in gmem, converted to fp16 during the smem store.
// ===========================================================================
__device__ __forceinline__ void mma_f16(float* d, const uint32_t* a, uint2 b) {
  asm volatile(
      "mma.sync.aligned.m16n8k16.row.col.f32.f16.f16.f32 "
      "{%0,%1,%2,%3}, {%4,%5,%6,%7}, {%8,%9}, {%0,%1,%2,%3};\n"
      : "+f"(d[0]), "+f"(d[1]), "+f"(d[2]), "+f"(d[3])
      : "r"(a[0]), "r"(a[1]), "r"(a[2]), "r"(a[3]), "r"(b.x), "r"(b.y));
}

#define GSM_BYTES ((2 * 128 * 40 + 2 * 64 * 40) * 4)

template<bool A_FLOAT, bool HALF_OUT>
__global__ __launch_bounds__(256, 2) void h16gemm_k(
    const void* __restrict__ Av, const __half* __restrict__ B,
    const float* __restrict__ bias, void* __restrict__ Cv,
    int M, int N, int K)
{
  extern __shared__ uint32_t smdyn[];
  uint32_t (*Asm)[40] = (uint32_t(*)[40])smdyn;                  // 2 x 128
  uint32_t (*Bsm)[40] = (uint32_t(*)[40])(smdyn + 2 * 128 * 40); // 2 x 64

  const int t = threadIdx.x;
  const int lane = t & 31, w = t >> 5;
  const int wm = (w & 3) * 32, wn = (w >> 2) * 32;
  const int g = lane >> 2, c = lane & 3;
  const int row0 = blockIdx.y * 128, col0 = blockIdx.x * 64;

  const int arow = t >> 1, as = t & 1;
  const int brow = t >> 2, bq = t & 3, bs = bq >> 1, bl = bq & 1;

  const float*  pAf = (const float*)Av  + (size_t)(row0 + arow) * K + as * 16;
  const __half* pAh = (const __half*)Av + (size_t)(row0 + arow) * K + as * 16;
  const __half* pB  = B + (size_t)(col0 + brow) * K + bs * 16 + bl * 8;

  float4 fa0, fa1, fa2, fa3;
  uint4  qa0, qa1;
  uint4  qb;

  if (A_FLOAT) {
    fa0 = *(const float4*)(pAf);
    fa1 = *(const float4*)(pAf + 4);
    fa2 = *(const float4*)(pAf + 8);
    fa3 = *(const float4*)(pAf + 12);
  } else {
    qa0 = *(const uint4*)(pAh);
    qa1 = *(const uint4*)(pAh + 8);
  }
  qb = *(const uint4*)(pB);

  auto storeA = [&](uint32_t (*An)[40]) {
    uint32_t* d = &An[arow][as * 8];
    if (A_FLOAT) {
      d[0] = h2u(__floats2half2_rn(fa0.x, fa0.y));
      d[2] = h2u(__floats2half2_rn(fa0.z, fa0.w));
      d[4] = h2u(__floats2half2_rn(fa1.x, fa1.y));
      d[6] = h2u(__floats2half2_rn(fa1.z, fa1.w));
      d[1] = h2u(__floats2half2_rn(fa2.x, fa2.y));
      d[3] = h2u(__floats2half2_rn(fa2.z, fa2.w));
      d[5] = h2u(__floats2half2_rn(fa3.x, fa3.y));
      d[7] = h2u(__floats2half2_rn(fa3.z, fa3.w));
    } else {
      d[0]=qa0.x; d[2]=qa0.y; d[4]=qa0.z; d[6]=qa0.w;
      d[1]=qa1.x; d[3]=qa1.y; d[5]=qa1.z; d[7]=qa1.w;
    }
  };
  auto storeB = [&](uint32_t (*Bn)[40]) {
    uint32_t* e = &Bn[brow][bs * 8 + bl];
    e[0]=qb.x; e[2]=qb.y; e[4]=qb.z; e[6]=qb.w;
  };

  storeA(Asm);
  storeB(Bsm);
  __syncthreads();

  float acc[2][4][4] = {};
  int s = 0;

  for (int k0 = 0; k0 < K; k0 += 32) {
    const bool nxt = (k0 + 32 < K);
    if (nxt) {
      if (A_FLOAT) {
        fa0 = *(const float4*)(pAf + k0 + 32);
        fa1 = *(const float4*)(pAf + k0 + 36);
        fa2 = *(const float4*)(pAf + k0 + 40);
        fa3 = *(const float4*)(pAf + k0 + 44);
      } else {
        qa0 = *(const uint4*)(pAh + k0 + 32);
        qa1 = *(const uint4*)(pAh + k0 + 40);
      }
      qb = *(const uint4*)(pB + k0 + 32);
    }
    const uint32_t (*Ac)[40] = Asm + s * 128;
    const uint32_t (*Bc)[40] = Bsm + s * 64;

    #pragma unroll
    for (int ks = 0; ks < 2; ks++) {
      uint32_t af[2][4];
      uint2 bf[4];
      #pragma unroll
      for (int mi = 0; mi < 2; mi++) {
        uint2 lo = *(const uint2*)&Ac[wm + mi * 16 + g][ks * 8 + 2 * c];
        uint2 hi = *(const uint2*)&Ac[wm + mi * 16 + g + 8][ks * 8 + 2 * c];
        af[mi][0] = lo.x; af[mi][1] = hi.x; af[mi][2] = lo.y; af[mi][3] = hi.y;
      }
      #pragma unroll
      for (int ni = 0; ni < 4; ni++)
        bf[ni] = *(const uint2*)&Bc[wn + ni * 8 + g][ks * 8 + 2 * c];
      #pragma unroll
      for (int mi = 0; mi < 2; mi++)
        #pragma unroll
        for (int ni = 0; ni < 4; ni++)
          mma_f16(acc[mi][ni], af[mi], bf[ni]);
    }

    if (nxt) {
      storeA(Asm + (s ^ 1) * 128);
      storeB(Bsm + (s ^ 1) * 64);
      __syncthreads();
      s ^= 1;
    }
  }

  #pragma unroll
  for (int mi = 0; mi < 2; mi++) {
    int r = row0 + wm + mi * 16 + g;
    #pragma unroll
    for (int ni = 0; ni < 4; ni++) {
      int cc = col0 + wn + ni * 8 + 2 * c;
      float2 bv = *(const float2*)(bias + cc);
      float* d = acc[mi][ni];
      if (HALF_OUT) {
        __half* Ch = (__half*)Cv;
        *(__half2*)(Ch + (size_t)r * N + cc) =
            __floats2half2_rn(d[0] + bv.x, d[1] + bv.y);
        *(__half2*)(Ch + (size_t)(r + 8) * N + cc) =
            __floats2half2_rn(d[2] + bv.x, d[3] + bv.y);
      } else {
        float* Cf = (float*)Cv;
        *(float2*)(Cf + (size_t)r * N + cc) =
            make_float2(d[0] + bv.x, d[1] + bv.y);
        *(float2*)(Cf + (size_t)(r + 8) * N + cc) =
            make_float2(d[2] + bv.x, d[3] + bv.y);
      }
    }
  }
}

// ---------------------------------------------------------------------------
// Merged fp32 SGEMM for BOTH score-path projections in one launch.
// z = 0,1: hsrc_h[n][head][128] (fp16)  = emb_src  @ att_W[head]
// z = 2,3: q[m][head][128]      (fp32)  = emb_dest @ wc[head]
// C[8192,128] = A[8192,64] @ B[64,128]. 64x64 tile, BK=16.
// ---------------------------------------------------------------------------
__global__ __launch_bounds__(256) void sgemm4_k(
    const float* __restrict__ emb_src, const float* __restrict__ emb_dest,
    const float* __restrict__ attW, const float* __restrict__ wc,
    __half* __restrict__ hsrc_h, float* __restrict__ q)
{
  const int z = blockIdx.z;
  const int head = z & 1, sel = z >> 1;
  const int N = HID, K = EMB;
  const float* A  = sel ? emb_dest : emb_src;
  const float* Bp = (sel ? wc : attW) + head * EMB * HID;

  __shared__ float As[16][68];
  __shared__ float Bs[16][68];

  const int t  = threadIdx.x;
  const int tx = t & 15;
  const int ty = t >> 4;
  const int row0 = blockIdx.y << 6;
  const int col0 = blockIdx.x << 6;

  const int aRow = t >> 2;
  const int aK   = (t & 3) << 2;
  const int bK   = t >> 4;
  const int bN   = (t & 15) << 2;

  float acc[4][4] = {};

  for (int k0 = 0; k0 < K; k0 += 16) {
    float4 a4 = *(const float4*)(A + (size_t)(row0 + aRow) * K + (k0 + aK));
    As[aK+0][aRow] = a4.x; As[aK+1][aRow] = a4.y;
    As[aK+2][aRow] = a4.z; As[aK+3][aRow] = a4.w;
    float4 b4 = *(const float4*)(Bp + (size_t)(k0 + bK) * N + (col0 + bN));
    *(float4*)&Bs[bK][bN] = b4;
    __syncthreads();
    #pragma unroll
    for (int k = 0; k < 16; k++) {
      float4 a = *(const float4*)&As[k][ty << 2];
      float4 b = *(const float4*)&Bs[k][tx << 2];
      acc[0][0] += a.x*b.x; acc[0][1] += a.x*b.y; acc[0][2] += a.x*b.z; acc[0][3] += a.x*b.w;
      acc[1][0] += a.y*b.x; acc[1][1] += a.y*b.y; acc[1][2] += a.y*b.z; acc[1][3] += a.y*b.w;
      acc[2][0] += a.z*b.x; acc[2][1] += a.z*b.y; acc[2][2] += a.z*b.z; acc[2][3] += a.z*b.w;
      acc[3][0] += a.w*b.x; acc[3][1] += a.w*b.y; acc[3][2] += a.w*b.z; acc[3][3] += a.w*b.w;
    }
    __syncthreads();
  }

  #pragma unroll
  for (int i = 0; i < 4; i++) {
    int row = row0 + (ty << 2) + i;
    int cc  = col0 + (tx << 2);
    if (sel) {
      // q fp32, interleaved [m][head][128]
      *(float4*)(q + (((size_t)row * 2 + head) << 7) + cc) =
          make_float4(acc[i][0], acc[i][1], acc[i][2], acc[i][3]);
    } else {
      // hsrc fp16, interleaved [n][head][128]
      uint2 hv = make_uint2(
          h2u(__floats2half2_rn(acc[i][0], acc[i][1])),
          h2u(__floats2half2_rn(acc[i][2], acc[i][3])));
      *(uint2*)(hsrc_h + (((size_t)row * 2 + head) << 7) + cc) = hv;
    }
  }
}

// ---------------------------------------------------------------------------
// Wc[h] = att_W[h] (64x128) @ att_W2[h] (128x128)
// ---------------------------------------------------------------------------
__global__ __launch_bounds__(128) void wc_kernel(
    const float* __restrict__ attW, const float* __restrict__ attW2,
    float* __restrict__ wc)
{
  const int b = blockIdx.x;              // 0..127
  const int h = b >> 6, e = b & 63;
  const int d = threadIdx.x;             // 0..127
  __shared__ float Wsh[HID];
  Wsh[d] = attW[h * EMB * HID + e * HID + d];
  __syncthreads();
  const float* W2 = attW2 + h * HID * HID;
  float s = 0.f;
  #pragma unroll 16
  for (int k = 0; k < HID; k++) s += Wsh[k] * W2[k * HID + d];
  wc[h * EMB * HID + e * HID + d] = s;
}

// ---------------------------------------------------------------------------
// Sparse masked attention, one block (256 threads) per destination row m.
// hsrc fp16 head-interleaved: one 512B contiguous read per score.
// Dual unnormalized accumulators; half2 gather with column-pair / j-parity
// thread split (256 threads, one extra barrier + 2KB exchange).
// nnz ~ Binomial(8192,0.01) = 82 +/- 9; SCAP=1024; chunked fallback for
// nnz > SCAP (never taken) keeps correctness.
// ---------------------------------------------------------------------------
__device__ __forceinline__ float2 score_exp_pair(
    int n, const float* qsh, const __half* __restrict__ hsrc_h, int lane)
{
  const uint2* kk = (const uint2*)(hsrc_h + ((size_t)n << 8));  // 256 halves
  uint2 u0 = kk[lane];        // head0: halves 4*lane .. 4*lane+3
  uint2 u1 = kk[32 + lane];   // head1
  const float4 a0 = ((const float4*)qsh)[lane];
  const float4 a1 = ((const float4*)qsh)[32 + lane];
  float2 p00 = __half22float2(*(__half2*)&u0.x);
  float2 p01 = __half22float2(*(__half2*)&u0.y);
  float2 p10 = __half22float2(*(__half2*)&u1.x);
  float2 p11 = __half22float2(*(__half2*)&u1.y);
  float s0 = a0.x*p00.x + a0.y*p00.y + a0.z*p01.x + a0.w*p01.y;
  float s1 = a1.x*p10.x + a1.y*p10.y + a1.z*p11.x + a1.w*p11.y;
  #pragma unroll
  for (int o = 16; o; o >>= 1) {
    s0 += __shfl_xor_sync(0xffffffffu, s0, o);
    s1 += __shfl_xor_sync(0xffffffffu, s1, o);
  }
  float e0 = expf(s0 > 0.f ? s0 : expm1f(s0));  // exp(elu(s))
  float e1 = expf(s1 > 0.f ? s1 : expm1f(s1));
  return make_float2(e0, e1);
}

#define SCAP 1024

__global__ __launch_bounds__(256) void attn_kernel(
    const float* __restrict__ bias,
    const float* __restrict__ q,            // [NDEST][2][128] fp32
    const __half* __restrict__ hsrc,        // [NSRC][2][128] fp16
    const __half* __restrict__ xh,          // [NSRC][TFD] fp16
    float* __restrict__ out)                // [NDEST][TFD]
{
  const int m = blockIdx.x;
  const int t = threadIdx.x;
  const int warp = t >> 5, lane = t & 31;

  __shared__ unsigned short sidx[SCAP];        // 2 KB
  __shared__ __align__(16) float qsh[2 * HID]; // 1 KB
  __shared__ float2 ecache[SCAP];              // 8 KB
  __shared__ __align__(16) float4 sm_ex[128];  // 2 KB
  __shared__ int s_warp[8];
  __shared__ float red[16];
  __shared__ float sZ0, sZ1;

  qsh[t] = q[((size_t)m << 8) + t];   // contiguous 1KB: [head0|head1]

  const float4* brow4 = (const float4*)(bias + (size_t)m * NSRC);

  // count nonzeros in this thread's 32 columns; warp-shuffle scan
  float4 v[8];
  int cnt = 0;
  #pragma unroll
  for (int i = 0; i < 8; i++) {
    v[i] = brow4[t * 8 + i];
    cnt += (v[i].x>0.f)+(v[i].y>0.f)+(v[i].z>0.f)+(v[i].w>0.f);
  }
  int inc = cnt;
  #pragma unroll
  for (int o = 1; o < 32; o <<= 1) {
    int u = __shfl_up_sync(0xffffffffu, inc, o);
    if (lane >= o) inc += u;
  }
  if (lane == 31) s_warp[warp] = inc;
  __syncthreads();
  int nnz = 0, woff = 0;
  #pragma unroll
  for (int i = 0; i < 8; i++) {
    int u = s_warp[i];
    nnz += u;
    if (i < warp) woff += u;
  }

  if (nnz == 0) {
    // all masked: softmax uniform over all sources (reference behavior)
    float acc = 0.f;
    for (int n = 0; n < NSRC; n++)
      acc += __half2float(xh[(size_t)n * TFD + t]);
    out[(size_t)m * TFD + t] = acc * (1.0f / NSRC);
    return;
  }

  if (nnz <= SCAP) {
    // ---------------- fast path ----------------
    int base = woff + inc - cnt;
    #pragma unroll
    for (int i = 0; i < 8; i++) {
      int b0 = t * 32 + i * 4;
      if (v[i].x > 0.f) sidx[base++] = (unsigned short)(b0 + 0);
      if (v[i].y > 0.f) sidx[base++] = (unsigned short)(b0 + 1);
      if (v[i].z > 0.f) sidx[base++] = (unsigned short)(b0 + 2);
      if (v[i].w > 0.f) sidx[base++] = (unsigned short)(b0 + 3);
    }
    __syncthreads();

    // scores -> ecache (8 warps)
    for (int j = warp; j < nnz; j += 8) {
      float2 e = score_exp_pair(sidx[j], qsh, hsrc, lane);
      if (lane == 0) ecache[j] = e;
    }
    __syncthreads();

    // warp 0 reduces Z while all threads gather (sZ read after barrier)
    if (warp == 0) {
      float z0 = 0.f, z1 = 0.f;
      for (int j = lane; j < nnz; j += 32) {
        float2 e = ecache[j];
        z0 += e.x; z1 += e.y;
      }
      #pragma unroll
      for (int o = 16; o; o >>= 1) {
        z0 += __shfl_xor_sync(0xffffffffu, z0, o);
        z1 += __shfl_xor_sync(0xffffffffu, z1, o);
      }
      if (lane == 0) { sZ0 = z0; sZ1 = z1; }
    }

    // half2 gather: thread owns column pair cp, j-parity jp
    const int cp = t & 127, jp = t >> 7;
    float a0x = 0.f, a0y = 0.f, a1x = 0.f, a1y = 0.f;
    int j = jp;
    for (; j + 6 < nnz; j += 8) {
      float2 x0 = __half22float2(*(const __half2*)(xh + (size_t)sidx[j+0] * TFD + 2*cp));
      float2 x1 = __half22float2(*(const __half2*)(xh + (size_t)sidx[j+2] * TFD + 2*cp));
      float2 x2 = __half22float2(*(const __half2*)(xh + (size_t)sidx[j+4] * TFD + 2*cp));
      float2 x3 = __half22float2(*(const __half2*)(xh + (size_t)sidx[j+6] * TFD + 2*cp));
      float2 e0 = ecache[j+0], e1 = ecache[j+2];
      float2 e2 = ecache[j+4], e3 = ecache[j+6];
      a0x += e0.x*x0.x + e1.x*x1.x + e2.x*x2.x + e3.x*x3.x;
      a0y += e0.x*x0.y + e1.x*x1.y + e2.x*x2.y + e3.x*x3.y;
      a1x += e0.y*x0.x + e1.y*x1.x + e2.y*x2.x + e3.y*x3.x;
      a1y += e0.y*x0.y + e1.y*x1.y + e2.y*x2.y + e3.y*x3.y;
    }
    for (; j < nnz; j += 2) {
      float2 x = __half22float2(*(const __half2*)(xh + (size_t)sidx[j] * TFD + 2*cp));
      float2 e = ecache[j];
      a0x += e.x*x.x; a0y += e.x*x.y;
      a1x += e.y*x.x; a1y += e.y*x.y;
    }
    __syncthreads();
    if (jp == 1) sm_ex[cp] = make_float4(a0x, a0y, a1x, a1y);
    __syncthreads();
    if (jp == 0) {
      float4 p = sm_ex[cp];
      float w0 = 0.5f / sZ0, w1 = 0.5f / sZ1;
      float2 o = make_float2((a0x + p.x) * w0 + (a1x + p.z) * w1,
                             (a0y + p.y) * w0 + (a1y + p.w) * w1);
      *(float2*)(out + (size_t)m * TFD + 2*cp) = o;
    }
    return;
  }

  // -------- fallback: nnz > SCAP, chunked single pass (never expected) -----
  float acc0 = 0.f, acc1 = 0.f;
  float zp0 = 0.f, zp1 = 0.f;
  for (int c0 = 0; c0 < NSRC; c0 += SCAP) {
    __syncthreads();  // protect sidx/ecache reuse
    float4 w0 = brow4[c0 / 4 + t];
    int ccnt = (w0.x>0.f)+(w0.y>0.f)+(w0.z>0.f)+(w0.w>0.f);
    int cinc = ccnt;
    #pragma unroll
    for (int o = 1; o < 32; o <<= 1) {
      int u = __shfl_up_sync(0xffffffffu, cinc, o);
      if (lane >= o) cinc += u;
    }
    if (lane == 31) s_warp[warp] = cinc;
    __syncthreads();
    int cn = 0, cwoff = 0;
    #pragma unroll
    for (int i = 0; i < 8; i++) {
      int u = s_warp[i];
      cn += u;
      if (i < warp) cwoff += u;
    }
    int base = cwoff + cinc - ccnt;
    int b0 = c0 + t * 4;
    if (w0.x > 0.f) sidx[base++] = (unsigned short)(b0 + 0);
    if (w0.y > 0.f) sidx[base++] = (unsigned short)(b0 + 1);
    if (w0.z > 0.f) sidx[base++] = (unsigned short)(b0 + 2);
    if (w0.w > 0.f) sidx[base++] = (unsigned short)(b0 + 3);
    __syncthreads();

    for (int j = warp; j < cn; j += 8) {
      float2 e = score_exp_pair(sidx[j], qsh, hsrc, lane);
      if (lane == 0) { ecache[j] = e; zp0 += e.x; zp1 += e.y; }
    }
    __syncthreads();
    for (int j = 0; j < cn; j++) {
      float2 e = ecache[j];
      float x = __half2float(xh[(size_t)sidx[j] * TFD + t]);
      acc0 += e.x * x; acc1 += e.y * x;
    }
  }
  if (lane == 0) { red[warp] = zp0; red[8 + warp] = zp1; }
  __syncthreads();
  if (t == 0) {
    float z0 = 0.f, z1 = 0.f;
    #pragma unroll
    for (int wi = 0; wi < 8; wi++) { z0 += red[wi]; z1 += red[8 + wi]; }
    sZ0 = z0; sZ1 = z1;
  }
  __syncthreads();
  out[(size_t)m * TFD + t] = acc0 * (0.5f / sZ0) + acc1 * (0.5f / sZ1);
}

// ---------------------------------------------------------------------------
extern "C" void kernel_launch(void* const* d_in, const int* in_sizes, int n_in,
                              void* d_out, int out_size)
{
  const float* bias        = (const float*)d_in[0];
  const float* emb_dest    = (const float*)d_in[1];
  const float* emb_src     = (const float*)d_in[2];
  const float* feature_src = (const float*)d_in[3];
  const float* fc_W        = (const float*)d_in[4];
  const float* fc_b        = (const float*)d_in[5];
  const float* dec_W       = (const float*)d_in[6];
  const float* dec_b       = (const float*)d_in[7];
  const float* att_W       = (const float*)d_in[8];
  const float* att_W2      = (const float*)d_in[9];

  float* out_re  = (float*)d_out;
  float* out_hat = out_re + (size_t)NDEST * TFD;

  __half *fcW_h, *decW_h, *trans_h, *hsrc_h;
  float *qp, *wc;
  cudaGetSymbolAddress((void**)&fcW_h, g_fcW_h);
  cudaGetSymbolAddress((void**)&decW_h, g_decW_h);
  cudaGetSymbolAddress((void**)&trans_h, g_trans_h);
  cudaGetSymbolAddress((void**)&hsrc_h, g_hsrc_h);
  cudaGetSymbolAddress((void**)&qp, g_q);
  cudaGetSymbolAddress((void**)&wc, g_wc);

  cudaFuncSetAttribute(h16gemm_k<true, true>,
                       cudaFuncAttributeMaxDynamicSharedMemorySize, GSM_BYTES);
  cudaFuncSetAttribute(h16gemm_k<false, false>,
                       cudaFuncAttributeMaxDynamicSharedMemorySize, GSM_BYTES);

  // small weight conversions to fp16
  f2h_kernel<<<(TFD*FEATD/4 + 255)/256, 256>>>(fc_W, fcW_h, TFD*FEATD);
  f2h_kernel<<<(FEATD*TFD/4 + 255)/256, 256>>>(dec_W, decW_h, FEATD*TFD);

  // Wc[h] = att_W[h] @ att_W2[h]
  wc_kernel<<<128, 128>>>(att_W, att_W2, wc);

  // hsrc (fp16 interleaved) + q (fp32 interleaved) in one batched launch
  sgemm4_k<<<dim3(HID / 64, NSRC / 64, 4), 256>>>(
      emb_src, emb_dest, att_W, wc, hsrc_h, qp);

  // transformed = feature_src @ fc_W^T + fc_b (fp32 A converted in-kernel)
  h16gemm_k<true, true><<<dim3(TFD / 64, NSRC / 128), 256, GSM_BYTES>>>(
      feature_src, fcW_h, fc_b, trans_h, NSRC, TFD, FEATD);

  // feature_hat = transformed @ dec_W^T + dec_b
  h16gemm_k<false, false><<<dim3(FEATD / 64, NSRC / 128), 256, GSM_BYTES>>>(
      trans_h, decW_h, dec_b, out_hat, NSRC, FEATD, TFD);

  // sparse masked attention + aggregation
  attn_kernel<<<NDEST, 256>>>(bias, qp, hsrc_h, trans_h, out_re);
}

// round 12
// speedup vs baseline: 1.2997x; 1.0356x over previous
#include <cuda_runtime.h>
#include <cuda_fp16.h>
#include <math.h>
#include <stdint.h>

#define NDEST 8192
#define NSRC  8192
#define FEATD 1024
#define TFD   256
#define EMB   64
#define HID   128
#define HEADS 2
#define SCAP  1024

// scratch (static device arrays: allocation-free)
__device__ __half g_fcW_h[TFD * FEATD];                  // 0.5 MB
__device__ __half g_decW_h[FEATD * TFD];                 // 0.5 MB
__device__ __half g_trans_h[(size_t)NSRC * TFD];         // 4 MB
__device__ __half g_hsrc_h[(size_t)NSRC * 2 * HID];      // 4 MB, [n][head][128]
__device__ float  g_q[(size_t)NDEST * 2 * HID];          // 8 MB, [m][head][128]
__device__ float  g_wc[HEADS * EMB * HID];               // 64 KB
__device__ float  g_w[(size_t)NDEST * SCAP];             // 32 MB CSR weights
__device__ unsigned short g_idx[(size_t)NDEST * SCAP];   // 16 MB CSR indices
__device__ int    g_cnt[NDEST];                          // 32 KB

// ---------------------------------------------------------------------------
// f32 -> f16 conversion (n multiple of 4) — weights only (small)
// ---------------------------------------------------------------------------
__global__ void f2h_kernel(const float* __restrict__ src,
                           __half* __restrict__ dst, int n)
{
  int i = (blockIdx.x * blockDim.x + threadIdx.x) * 4;
  if (i < n) {
    float4 v = *(const float4*)(src + i);
    *(__half2*)(dst + i)     = __floats2half2_rn(v.x, v.y);
    *(__half2*)(dst + i + 2) = __floats2half2_rn(v.z, v.w);
  }
}

__device__ __forceinline__ uint32_t h2u(__half2 h) {
  return *(uint32_t*)&h;
}

// ===========================================================================
// FP16 tensor-core GEMM:  C[M,N] = A[M,K] @ B[N,K]^T (+ bias[N])
// mma.m16n8k16.f16, fp32 accum. BM=128, BN=64, BK=32, 256 threads, 8 warps.
// Double-buffered smem; pair-permuted layout (LDS.64 fragments, stride 40).
// A_FLOAT: A fp32 in gmem, converted to fp16 during the smem store.
// ===========================================================================
__device__ __forceinline__ void mma_f16(float* d, const uint32_t* a, uint2 b) {
  asm volatile(
      "mma.sync.aligned.m16n8k16.row.col.f32.f16.f16.f32 "
      "{%0,%1,%2,%3}, {%4,%5,%6,%7}, {%8,%9}, {%0,%1,%2,%3};\n"
      : "+f"(d[0]), "+f"(d[1]), "+f"(d[2]), "+f"(d[3])
      : "r"(a[0]), "r"(a[1]), "r"(a[2]), "r"(a[3]), "r"(b.x), "r"(b.y));
}

#define GSM_BYTES ((2 * 128 * 40 + 2 * 64 * 40) * 4)

template<bool A_FLOAT, bool HALF_OUT>
__global__ __launch_bounds__(256, 2) void h16gemm_k(
    const void* __restrict__ Av, const __half* __restrict__ B,
    const float* __restrict__ bias, void* __restrict__ Cv,
    int M, int N, int K)
{
  extern __shared__ uint32_t smdyn[];
  uint32_t (*Asm)[40] = (uint32_t(*)[40])smdyn;                  // 2 x 128
  uint32_t (*Bsm)[40] = (uint32_t(*)[40])(smdyn + 2 * 128 * 40); // 2 x 64

  const int t = threadIdx.x;
  const int lane = t & 31, w = t >> 5;
  const int wm = (w & 3) * 32, wn = (w >> 2) * 32;
  const int g = lane >> 2, c = lane & 3;
  const int row0 = blockIdx.y * 128, col0 = blockIdx.x * 64;

  const int arow = t >> 1, as = t & 1;
  const int brow = t >> 2, bq = t & 3, bs = bq >> 1, bl = bq & 1;

  const float*  pAf = (const float*)Av  + (size_t)(row0 + arow) * K + as * 16;
  const __half* pAh = (const __half*)Av + (size_t)(row0 + arow) * K + as * 16;
  const __half* pB  = B + (size_t)(col0 + brow) * K + bs * 16 + bl * 8;

  float4 fa0, fa1, fa2, fa3;
  uint4  qa0, qa1;
  uint4  qb;

  if (A_FLOAT) {
    fa0 = *(const float4*)(pAf);
    fa1 = *(const float4*)(pAf + 4);
    fa2 = *(const float4*)(pAf + 8);
    fa3 = *(const float4*)(pAf + 12);
  } else {
    qa0 = *(const uint4*)(pAh);
    qa1 = *(const uint4*)(pAh + 8);
  }
  qb = *(const uint4*)(pB);

  auto storeA = [&](uint32_t (*An)[40]) {
    uint32_t* d = &An[arow][as * 8];
    if (A_FLOAT) {
      d[0] = h2u(__floats2half2_rn(fa0.x, fa0.y));
      d[2] = h2u(__floats2half2_rn(fa0.z, fa0.w));
      d[4] = h2u(__floats2half2_rn(fa1.x, fa1.y));
      d[6] = h2u(__floats2half2_rn(fa1.z, fa1.w));
      d[1] = h2u(__floats2half2_rn(fa2.x, fa2.y));
      d[3] = h2u(__floats2half2_rn(fa2.z, fa2.w));
      d[5] = h2u(__floats2half2_rn(fa3.x, fa3.y));
      d[7] = h2u(__floats2half2_rn(fa3.z, fa3.w));
    } else {
      d[0]=qa0.x; d[2]=qa0.y; d[4]=qa0.z; d[6]=qa0.w;
      d[1]=qa1.x; d[3]=qa1.y; d[5]=qa1.z; d[7]=qa1.w;
    }
  };
  auto storeB = [&](uint32_t (*Bn)[40]) {
    uint32_t* e = &Bn[brow][bs * 8 + bl];
    e[0]=qb.x; e[2]=qb.y; e[4]=qb.z; e[6]=qb.w;
  };

  storeA(Asm);
  storeB(Bsm);
  __syncthreads();

  float acc[2][4][4] = {};
  int s = 0;

  for (int k0 = 0; k0 < K; k0 += 32) {
    const bool nxt = (k0 + 32 < K);
    if (nxt) {
      if (A_FLOAT) {
        fa0 = *(const float4*)(pAf + k0 + 32);
        fa1 = *(const float4*)(pAf + k0 + 36);
        fa2 = *(const float4*)(pAf + k0 + 40);
        fa3 = *(const float4*)(pAf + k0 + 44);
      } else {
        qa0 = *(const uint4*)(pAh + k0 + 32);
        qa1 = *(const uint4*)(pAh + k0 + 40);
      }
      qb = *(const uint4*)(pB + k0 + 32);
    }
    const uint32_t (*Ac)[40] = Asm + s * 128;
    const uint32_t (*Bc)[40] = Bsm + s * 64;

    #pragma unroll
    for (int ks = 0; ks < 2; ks++) {
      uint32_t af[2][4];
      uint2 bf[4];
      #pragma unroll
      for (int mi = 0; mi < 2; mi++) {
        uint2 lo = *(const uint2*)&Ac[wm + mi * 16 + g][ks * 8 + 2 * c];
        uint2 hi = *(const uint2*)&Ac[wm + mi * 16 + g + 8][ks * 8 + 2 * c];
        af[mi][0] = lo.x; af[mi][1] = hi.x; af[mi][2] = lo.y; af[mi][3] = hi.y;
      }
      #pragma unroll
      for (int ni = 0; ni < 4; ni++)
        bf[ni] = *(const uint2*)&Bc[wn + ni * 8 + g][ks * 8 + 2 * c];
      #pragma unroll
      for (int mi = 0; mi < 2; mi++)
        #pragma unroll
        for (int ni = 0; ni < 4; ni++)
          mma_f16(acc[mi][ni], af[mi], bf[ni]);
    }

    if (nxt) {
      storeA(Asm + (s ^ 1) * 128);
      storeB(Bsm + (s ^ 1) * 64);
      __syncthreads();
      s ^= 1;
    }
  }

  #pragma unroll
  for (int mi = 0; mi < 2; mi++) {
    int r = row0 + wm + mi * 16 + g;
    #pragma unroll
    for (int ni = 0; ni < 4; ni++) {
      int cc = col0 + wn + ni * 8 + 2 * c;
      float2 bv = *(const float2*)(bias + cc);
      float* d = acc[mi][ni];
      if (HALF_OUT) {
        __half* Ch = (__half*)Cv;
        *(__half2*)(Ch + (size_t)r * N + cc) =
            __floats2half2_rn(d[0] + bv.x, d[1] + bv.y);
        *(__half2*)(Ch + (size_t)(r + 8) * N + cc) =
            __floats2half2_rn(d[2] + bv.x, d[3] + bv.y);
      } else {
        float* Cf = (float*)Cv;
        *(float2*)(Cf + (size_t)r * N + cc) =
            make_float2(d[0] + bv.x, d[1] + bv.y);
        *(float2*)(Cf + (size_t)(r + 8) * N + cc) =
            make_float2(d[2] + bv.x, d[3] + bv.y);
      }
    }
  }
}

// ---------------------------------------------------------------------------
// Merged fp32 SGEMM for BOTH score-path projections in one launch.
// z = 0,1: hsrc_h[n][head][128] (fp16)  = emb_src  @ att_W[head]
// z = 2,3: q[m][head][128]      (fp32)  = emb_dest @ wc[head]
// ---------------------------------------------------------------------------
__global__ __launch_bounds__(256) void sgemm4_k(
    const float* __restrict__ emb_src, const float* __restrict__ emb_dest,
    const float* __restrict__ attW, const float* __restrict__ wc,
    __half* __restrict__ hsrc_h, float* __restrict__ q)
{
  const int z = blockIdx.z;
  const int head = z & 1, sel = z >> 1;
  const int N = HID, K = EMB;
  const float* A  = sel ? emb_dest : emb_src;
  const float* Bp = (sel ? wc : attW) + head * EMB * HID;

  __shared__ float As[16][68];
  __shared__ float Bs[16][68];

  const int t  = threadIdx.x;
  const int tx = t & 15;
  const int ty = t >> 4;
  const int row0 = blockIdx.y << 6;
  const int col0 = blockIdx.x << 6;

  const int aRow = t >> 2;
  const int aK   = (t & 3) << 2;
  const int bK   = t >> 4;
  const int bN   = (t & 15) << 2;

  float acc[4][4] = {};

  for (int k0 = 0; k0 < K; k0 += 16) {
    float4 a4 = *(const float4*)(A + (size_t)(row0 + aRow) * K + (k0 + aK));
    As[aK+0][aRow] = a4.x; As[aK+1][aRow] = a4.y;
    As[aK+2][aRow] = a4.z; As[aK+3][aRow] = a4.w;
    float4 b4 = *(const float4*)(Bp + (size_t)(k0 + bK) * N + (col0 + bN));
    *(float4*)&Bs[bK][bN] = b4;
    __syncthreads();
    #pragma unroll
    for (int k = 0; k < 16; k++) {
      float4 a = *(const float4*)&As[k][ty << 2];
      float4 b = *(const float4*)&Bs[k][tx << 2];
      acc[0][0] += a.x*b.x; acc[0][1] += a.x*b.y; acc[0][2] += a.x*b.z; acc[0][3] += a.x*b.w;
      acc[1][0] += a.y*b.x; acc[1][1] += a.y*b.y; acc[1][2] += a.y*b.z; acc[1][3] += a.y*b.w;
      acc[2][0] += a.z*b.x; acc[2][1] += a.z*b.y; acc[2][2] += a.z*b.z; acc[2][3] += a.z*b.w;
      acc[3][0] += a.w*b.x; acc[3][1] += a.w*b.y; acc[3][2] += a.w*b.z; acc[3][3] += a.w*b.w;
    }
    __syncthreads();
  }

  #pragma unroll
  for (int i = 0; i < 4; i++) {
    int row = row0 + (ty << 2) + i;
    int cc  = col0 + (tx << 2);
    if (sel) {
      *(float4*)(q + (((size_t)row * 2 + head) << 7) + cc) =
          make_float4(acc[i][0], acc[i][1], acc[i][2], acc[i][3]);
    } else {
      uint2 hv = make_uint2(
          h2u(__floats2half2_rn(acc[i][0], acc[i][1])),
          h2u(__floats2half2_rn(acc[i][2], acc[i][3])));
      *(uint2*)(hsrc_h + (((size_t)row * 2 + head) << 7) + cc) = hv;
    }
  }
}

// ---------------------------------------------------------------------------
// Wc[h] = att_W[h] (64x128) @ att_W2[h] (128x128)
// ---------------------------------------------------------------------------
__global__ __launch_bounds__(128) void wc_kernel(
    const float* __restrict__ attW, const float* __restrict__ attW2,
    float* __restrict__ wc)
{
  const int b = blockIdx.x;              // 0..127
  const int h = b >> 6, e = b & 63;
  const int d = threadIdx.x;             // 0..127
  __shared__ float Wsh[HID];
  Wsh[d] = attW[h * EMB * HID + e * HID + d];
  __syncthreads();
  const float* W2 = attW2 + h * HID * HID;
  float s = 0.f;
  #pragma unroll 16
  for (int k = 0; k < HID; k++) s += Wsh[k] * W2[k * HID + d];
  wc[h * EMB * HID + e * HID + d] = s;
}

// ---------------------------------------------------------------------------
// score helper: exp(elu(q.k)) for both heads of source n (warp-collective)
// ---------------------------------------------------------------------------
__device__ __forceinline__ float2 score_exp_pair(
    int n, const float* qsh, const __half* __restrict__ hsrc_h, int lane)
{
  const uint2* kk = (const uint2*)(hsrc_h + ((size_t)n << 8));  // 256 halves
  uint2 u0 = kk[lane];
  uint2 u1 = kk[32 + lane];
  const float4 a0 = ((const float4*)qsh)[lane];
  const float4 a1 = ((const float4*)qsh)[32 + lane];
  float2 p00 = __half22float2(*(__half2*)&u0.x);
  float2 p01 = __half22float2(*(__half2*)&u0.y);
  float2 p10 = __half22float2(*(__half2*)&u1.x);
  float2 p11 = __half22float2(*(__half2*)&u1.y);
  float s0 = a0.x*p00.x + a0.y*p00.y + a0.z*p01.x + a0.w*p01.y;
  float s1 = a1.x*p10.x + a1.y*p10.y + a1.z*p11.x + a1.w*p11.y;
  #pragma unroll
  for (int o = 16; o; o >>= 1) {
    s0 += __shfl_xor_sync(0xffffffffu, s0, o);
    s1 += __shfl_xor_sync(0xffffffffu, s1, o);
  }
  float e0 = expf(s0 > 0.f ? s0 : expm1f(s0));  // exp(elu(s))
  float e1 = expf(s1 > 0.f ? s1 : expm1f(s1));
  return make_float2(e0, e1);
}

// ---------------------------------------------------------------------------
// Kernel 1: per dest row m — bias scan, compact, scores, softmax normalize.
// Writes CSR: w[m][j] = e0/(2*Z0) + e1/(2*Z1), idx[m][j], cnt[m].
// nnz > SCAP or nnz == 0 handled by gather_kernel fallbacks (never taken).
// ---------------------------------------------------------------------------
__global__ __launch_bounds__(256) void score_kernel(
    const float* __restrict__ bias,
    const float* __restrict__ q,            // [NDEST][2][128] fp32
    const __half* __restrict__ hsrc,        // [NSRC][2][128] fp16
    float* __restrict__ wout,               // [NDEST][SCAP]
    unsigned short* __restrict__ idxout,    // [NDEST][SCAP]
    int* __restrict__ cntout)
{
  const int m = blockIdx.x;
  const int t = threadIdx.x;
  const int warp = t >> 5, lane = t & 31;

  __shared__ unsigned short sidx[SCAP];        // 2 KB
  __shared__ __align__(16) float qsh[2 * HID]; // 1 KB
  __shared__ float2 ecache[SCAP];              // 8 KB
  __shared__ int s_warp[8];
  __shared__ float sZ0, sZ1;

  qsh[t] = q[((size_t)m << 8) + t];

  const float4* brow4 = (const float4*)(bias + (size_t)m * NSRC);

  float4 v[8];
  int cnt = 0;
  #pragma unroll
  for (int i = 0; i < 8; i++) {
    v[i] = brow4[t * 8 + i];
    cnt += (v[i].x>0.f)+(v[i].y>0.f)+(v[i].z>0.f)+(v[i].w>0.f);
  }
  int inc = cnt;
  #pragma unroll
  for (int o = 1; o < 32; o <<= 1) {
    int u = __shfl_up_sync(0xffffffffu, inc, o);
    if (lane >= o) inc += u;
  }
  if (lane == 31) s_warp[warp] = inc;
  __syncthreads();
  int nnz = 0, woff = 0;
  #pragma unroll
  for (int i = 0; i < 8; i++) {
    int u = s_warp[i];
    nnz += u;
    if (i < warp) woff += u;
  }

  if (nnz == 0 || nnz > SCAP) {
    if (t == 0) cntout[m] = nnz;   // gather_kernel fallback handles it
    return;
  }

  int base = woff + inc - cnt;
  #pragma unroll
  for (int i = 0; i < 8; i++) {
    int b0 = t * 32 + i * 4;
    if (v[i].x > 0.f) sidx[base++] = (unsigned short)(b0 + 0);
    if (v[i].y > 0.f) sidx[base++] = (unsigned short)(b0 + 1);
    if (v[i].z > 0.f) sidx[base++] = (unsigned short)(b0 + 2);
    if (v[i].w > 0.f) sidx[base++] = (unsigned short)(b0 + 3);
  }
  __syncthreads();

  // scores (8 warps, j-strided, unroll 2 for MLP)
  for (int j = warp; j < nnz; j += 16) {
    float2 e0 = score_exp_pair(sidx[j], qsh, hsrc, lane);
    float2 e1 = make_float2(0.f, 0.f);
    int j2 = j + 8;
    if (j2 < nnz) e1 = score_exp_pair(sidx[j2], qsh, hsrc, lane);
    if (lane == 0) {
      ecache[j] = e0;
      if (j2 < nnz) ecache[j2] = e1;
    }
  }
  __syncthreads();

  // warp 0 reduces Z
  if (warp == 0) {
    float z0 = 0.f, z1 = 0.f;
    for (int j = lane; j < nnz; j += 32) {
      float2 e = ecache[j];
      z0 += e.x; z1 += e.y;
    }
    #pragma unroll
    for (int o = 16; o; o >>= 1) {
      z0 += __shfl_xor_sync(0xffffffffu, z0, o);
      z1 += __shfl_xor_sync(0xffffffffu, z1, o);
    }
    if (lane == 0) { sZ0 = z0; sZ1 = z1; }
  }
  __syncthreads();
  const float inv0 = 0.5f / sZ0;
  const float inv1 = 0.5f / sZ1;

  float* wrow = wout + (size_t)m * SCAP;
  unsigned short* irow = idxout + (size_t)m * SCAP;
  for (int j = t; j < nnz; j += 256) {
    float2 e = ecache[j];
    wrow[j] = e.x * inv0 + e.y * inv1;
    irow[j] = sidx[j];
  }
  if (t == 0) cntout[m] = nnz;
}

// ---------------------------------------------------------------------------
// Kernel 2: per dest row m — pure CSR gather. 128 threads, each owns one
// half2 column pair. Deep unrolled (8 rows in flight). High occupancy.
// Fallbacks (cnt==0 uniform softmax; cnt>SCAP full recompute) keep exactness.
// ---------------------------------------------------------------------------
__global__ __launch_bounds__(128) void gather_kernel(
    const float* __restrict__ w,            // [NDEST][SCAP]
    const unsigned short* __restrict__ idx, // [NDEST][SCAP]
    const int* __restrict__ cnt,
    const __half* __restrict__ xh,          // [NSRC][TFD] fp16
    const float* __restrict__ bias,
    const float* __restrict__ q,
    const __half* __restrict__ hsrc,
    float* __restrict__ out)                // [NDEST][TFD]
{
  const int m = blockIdx.x;
  const int t = threadIdx.x;                // 0..127; cols 2t, 2t+1
  const int n = cnt[m];

  __shared__ float wsh[SCAP];               // 4 KB
  __shared__ unsigned short ish[SCAP];      // 2 KB

  if (n > 0 && n <= SCAP) {
    const float* wrow = w + (size_t)m * SCAP;
    const unsigned short* irow = idx + (size_t)m * SCAP;
    for (int j = t; j < n; j += 128) {
      wsh[j] = wrow[j];
      ish[j] = irow[j];
    }
    __syncthreads();

    float ax = 0.f, ay = 0.f;
    int j = 0;
    for (; j + 8 <= n; j += 8) {
      int r0 = ish[j+0] * TFD, r1 = ish[j+1] * TFD;
      int r2 = ish[j+2] * TFD, r3 = ish[j+3] * TFD;
      int r4 = ish[j+4] * TFD, r5 = ish[j+5] * TFD;
      int r6 = ish[j+6] * TFD, r7 = ish[j+7] * TFD;
      float2 x0 = __half22float2(*(const __half2*)(xh + r0 + 2*t));
      float2 x1 = __half22float2(*(const __half2*)(xh + r1 + 2*t));
      float2 x2 = __half22float2(*(const __half2*)(xh + r2 + 2*t));
      float2 x3 = __half22float2(*(const __half2*)(xh + r3 + 2*t));
      float2 x4 = __half22float2(*(const __half2*)(xh + r4 + 2*t));
      float2 x5 = __half22float2(*(const __half2*)(xh + r5 + 2*t));
      float2 x6 = __half22float2(*(const __half2*)(xh + r6 + 2*t));
      float2 x7 = __half22float2(*(const __half2*)(xh + r7 + 2*t));
      float w0 = wsh[j+0], w1 = wsh[j+1], w2 = wsh[j+2], w3 = wsh[j+3];
      float w4 = wsh[j+4], w5 = wsh[j+5], w6 = wsh[j+6], w7 = wsh[j+7];
      ax += w0*x0.x + w1*x1.x + w2*x2.x + w3*x3.x
          + w4*x4.x + w5*x5.x + w6*x6.x + w7*x7.x;
      ay += w0*x0.y + w1*x1.y + w2*x2.y + w3*x3.y
          + w4*x4.y + w5*x5.y + w6*x6.y + w7*x7.y;
    }
    for (; j < n; j++) {
      float2 x = __half22float2(*(const __half2*)(xh + ish[j] * TFD + 2*t));
      float wv = wsh[j];
      ax += wv * x.x; ay += wv * x.y;
    }
    *(float2*)(out + (size_t)m * TFD + 2*t) = make_float2(ax, ay);
    return;
  }

  if (n == 0) {
    // all masked: softmax uniform over all sources (reference behavior)
    float ax = 0.f, ay = 0.f;
    for (int r = 0; r < NSRC; r++) {
      float2 x = __half22float2(*(const __half2*)(xh + (size_t)r * TFD + 2*t));
      ax += x.x; ay += x.y;
    }
    *(float2*)(out + (size_t)m * TFD + 2*t) =
        make_float2(ax * (1.0f / NSRC), ay * (1.0f / NSRC));
    return;
  }

  // ---- n > SCAP: full chunked recompute (exact; never expected) ----
  const int warp = t >> 5, lane = t & 31;
  __shared__ __align__(16) float qsh[2 * HID];
  __shared__ float2 ecache2[SCAP];  // reuse budget: separate array (12KB tot)
  __shared__ int s_warp4[4];
  __shared__ float sZ0, sZ1;

  if (t < 256 && t < 2 * HID) { }  // placate compiler
  qsh[t] = q[((size_t)m << 8) + t];
  qsh[t + 128] = q[((size_t)m << 8) + t + 128];

  const float4* brow4 = (const float4*)(bias + (size_t)m * NSRC);
  float ax = 0.f, ay = 0.f;
  float zp0 = 0.f, zp1 = 0.f;

  for (int c0 = 0; c0 < NSRC; c0 += SCAP) {
    __syncthreads();
    // compact this chunk: 128 threads x 8 cols (2 float4)
    float4 v0 = brow4[c0 / 4 + t * 2];
    float4 v1 = brow4[c0 / 4 + t * 2 + 1];
    int ccnt = (v0.x>0.f)+(v0.y>0.f)+(v0.z>0.f)+(v0.w>0.f)
             + (v1.x>0.f)+(v1.y>0.f)+(v1.z>0.f)+(v1.w>0.f);
    int cinc = ccnt;
    #pragma unroll
    for (int o = 1; o < 32; o <<= 1) {
      int u = __shfl_up_sync(0xffffffffu, cinc, o);
      if (lane >= o) cinc += u;
    }
    if (lane == 31) s_warp4[warp] = cinc;
    __syncthreads();
    int cn = 0, cwoff = 0;
    #pragma unroll
    for (int i = 0; i < 4; i++) {
      int u = s_warp4[i];
      cn += u;
      if (i < warp) cwoff += u;
    }
    int base = cwoff + cinc - ccnt;
    int b0 = c0 + t * 8;
    if (v0.x > 0.f) ish[base++] = (unsigned short)(b0 + 0);
    if (v0.y > 0.f) ish[base++] = (unsigned short)(b0 + 1);
    if (v0.z > 0.f) ish[base++] = (unsigned short)(b0 + 2);
    if (v0.w > 0.f) ish[base++] = (unsigned short)(b0 + 3);
    if (v1.x > 0.f) ish[base++] = (unsigned short)(b0 + 4);
    if (v1.y > 0.f) ish[base++] = (unsigned short)(b0 + 5);
    if (v1.z > 0.f) ish[base++] = (unsigned short)(b0 + 6);
    if (v1.w > 0.f) ish[base++] = (unsigned short)(b0 + 7);
    __syncthreads();

    for (int j = warp; j < cn; j += 4) {
      float2 e = score_exp_pair(ish[j], qsh, hsrc, lane);
      if (lane == 0) { ecache2[j] = e; zp0 += e.x; zp1 += e.y; }
    }
    __syncthreads();
    for (int j = 0; j < cn; j++) {
      float2 e = ecache2[j];
      float2 x = __half22float2(*(const __half2*)(xh + ish[j] * TFD + 2*t));
      float ww = e.x;  // head0 weight (normalize later)
      ax += ww * x.x + 0.f;  // placeholder to keep dual accum
      ay += ww * x.y;
      // second head accumulated into separate sums below
      // (use ecache2 y with separate accumulators)
    }
    // second-head accumulation pass (small cost, never taken path)
    for (int j = 0; j < cn; j++) {
      float2 e = ecache2[j];
      float2 x = __half22float2(*(const __half2*)(xh + ish[j] * TFD + 2*t));
      zp0 += 0.f;  // no-op
      ax += 0.f * e.y * x.x;  // head1 handled via wsh trick below
      (void)x;
    }
  }
  // NOTE: head1 handling folded incorrectly above would break exactness;
  // to stay exact we recompute head1 with normalized weights directly:
  // reduce Z across warps via lane0 partials
  {
    // gather lane0 partials (only lane 0 of each warp holds zp)
    __shared__ float zr[8];
    if (lane == 0) { zr[warp] = zp0; zr[4 + warp] = zp1; }
    __syncthreads();
    if (t == 0) {
      float z0 = 0.f, z1 = 0.f;
      #pragma unroll
      for (int i = 0; i < 4; i++) { z0 += zr[i]; z1 += zr[4 + i]; }
      sZ0 = z0; sZ1 = z1;
    }
    __syncthreads();
  }
  const float inv0 = 0.5f / sZ0;
  const float inv1 = 0.5f / sZ1;
  // full exact recompute with known Z (slow; never taken)
  float fx = 0.f, fy = 0.f;
  for (int c0 = 0; c0 < NSRC; c0 += SCAP) {
    __syncthreads();
    float4 v0 = brow4[c0 / 4 + t * 2];
    float4 v1 = brow4[c0 / 4 + t * 2 + 1];
    int ccnt = (v0.x>0.f)+(v0.y>0.f)+(v0.z>0.f)+(v0.w>0.f)
             + (v1.x>0.f)+(v1.y>0.f)+(v1.z>0.f)+(v1.w>0.f);
    int cinc = ccnt;
    #pragma unroll
    for (int o = 1; o < 32; o <<= 1) {
      int u = __shfl_up_sync(0xffffffffu, cinc, o);
      if (lane >= o) cinc += u;
    }
    if (lane == 31) s_warp4[warp] = cinc;
    __syncthreads();
    int cn = 0, cwoff = 0;
    #pragma unroll
    for (int i = 0; i < 4; i++) {
      int u = s_warp4[i];
      cn += u;
      if (i < warp) cwoff += u;
    }
    int base = cwoff + cinc - ccnt;
    int b0 = c0 + t * 8;
    if (v0.x > 0.f) ish[base++] = (unsigned short)(b0 + 0);
    if (v0.y > 0.f) ish[base++] = (unsigned short)(b0 + 1);
    if (v0.z > 0.f) ish[base++] = (unsigned short)(b0 + 2);
    if (v0.w > 0.f) ish[base++] = (unsigned short)(b0 + 3);
    if (v1.x > 0.f) ish[base++] = (unsigned short)(b0 + 4);
    if (v1.y > 0.f) ish[base++] = (unsigned short)(b0 + 5);
    if (v1.z > 0.f) ish[base++] = (unsigned short)(b0 + 6);
    if (v1.w > 0.f) ish[base++] = (unsigned short)(b0 + 7);
    __syncthreads();
    for (int j = warp; j < cn; j += 4) {
      float2 e = score_exp_pair(ish[j], qsh, hsrc, lane);
      if (lane == 0) ecache2[j] = e;
    }
    __syncthreads();
    for (int j = 0; j < cn; j++) {
      float2 e = ecache2[j];
      float wv = e.x * inv0 + e.y * inv1;
      float2 x = __half22float2(*(const __half2*)(xh + ish[j] * TFD + 2*t));
      fx += wv * x.x; fy += wv * x.y;
    }
  }
  *(float2*)(out + (size_t)m * TFD + 2*t) = make_float2(fx, fy);
}

// ---------------------------------------------------------------------------
extern "C" void kernel_launch(void* const* d_in, const int* in_sizes, int n_in,
                              void* d_out, int out_size)
{
  const float* bias        = (const float*)d_in[0];
  const float* emb_dest    = (const float*)d_in[1];
  const float* emb_src     = (const float*)d_in[2];
  const float* feature_src = (const float*)d_in[3];
  const float* fc_W        = (const float*)d_in[4];
  const float* fc_b        = (const float*)d_in[5];
  const float* dec_W       = (const float*)d_in[6];
  const float* dec_b       = (const float*)d_in[7];
  const float* att_W       = (const float*)d_in[8];
  const float* att_W2      = (const float*)d_in[9];

  float* out_re  = (float*)d_out;
  float* out_hat = out_re + (size_t)NDEST * TFD;

  __half *fcW_h, *decW_h, *trans_h, *hsrc_h;
  float *qp, *wc, *wcsr;
  unsigned short* icsr;
  int* ccsr;
  cudaGetSymbolAddress((void**)&fcW_h, g_fcW_h);
  cudaGetSymbolAddress((void**)&decW_h, g_decW_h);
  cudaGetSymbolAddress((void**)&trans_h, g_trans_h);
  cudaGetSymbolAddress((void**)&hsrc_h, g_hsrc_h);
  cudaGetSymbolAddress((void**)&qp, g_q);
  cudaGetSymbolAddress((void**)&wc, g_wc);
  cudaGetSymbolAddress((void**)&wcsr, g_w);
  cudaGetSymbolAddress((void**)&icsr, g_idx);
  cudaGetSymbolAddress((void**)&ccsr, g_cnt);

  cudaFuncSetAttribute(h16gemm_k<true, true>,
                       cudaFuncAttributeMaxDynamicSharedMemorySize, GSM_BYTES);
  cudaFuncSetAttribute(h16gemm_k<false, false>,
                       cudaFuncAttributeMaxDynamicSharedMemorySize, GSM_BYTES);

  // small weight conversions to fp16
  f2h_kernel<<<(TFD*FEATD/4 + 255)/256, 256>>>(fc_W, fcW_h, TFD*FEATD);
  f2h_kernel<<<(FEATD*TFD/4 + 255)/256, 256>>>(dec_W, decW_h, FEATD*TFD);

  // Wc[h] = att_W[h] @ att_W2[h]
  wc_kernel<<<128, 128>>>(att_W, att_W2, wc);

  // hsrc (fp16 interleaved) + q (fp32 interleaved) in one batched launch
  sgemm4_k<<<dim3(HID / 64, NSRC / 64, 4), 256>>>(
      emb_src, emb_dest, att_W, wc, hsrc_h, qp);

  // scores -> CSR (independent of transformed; runs while nothing blocks it)
  score_kernel<<<NDEST, 256>>>(bias, qp, hsrc_h, wcsr, icsr, ccsr);

  // transformed = feature_src @ fc_W^T + fc_b (fp32 A converted in-kernel)
  h16gemm_k<true, true><<<dim3(TFD / 64, NSRC / 128), 256, GSM_BYTES>>>(
      feature_src, fcW_h, fc_b, trans_h, NSRC, TFD, FEATD);

  // feature_hat = transformed @ dec_W^T + dec_b
  h16gemm_k<false, false><<<dim3(FEATD / 64, NSRC / 128), 256, GSM_BYTES>>>(
      trans_h, decW_h, dec_b, out_hat, NSRC, FEATD, TFD);

  // CSR gather
  gather_kernel<<<NDEST, 128>>>(wcsr, icsr, ccsr, trans_h,
                                bias, qp, hsrc_h, out_re);
}